// round 1
// baseline (speedup 1.0000x reference)
#include <cuda_runtime.h>
#include <cstdint>
#include <cstddef>

#define TSTEPS 64
#define B_     512
#define NA     4
#define NIN    128
#define NH     512
#define NOUT   10
#define AH     2048      // NA * NH
#define K2     640       // NH + NIN

// ---------------- device scratch (no allocations allowed) ----------------
__device__ float g_CW1[(size_t)AH * AH];      // comm weights: [(j*NH+h), (i*NH+o)], pre-scaled by 0.1
__device__ float g_CW2[NA * K2 * NH];         // per agent: rows 0..511 = W_hh^T, rows 512..639 = W_in^T
__device__ float g_bias[AH];                  // b_in + b_hh, per (a, o)
__device__ float g_h[(size_t)B_ * AH];        // hidden state, layout (b, a*NH+o)
__device__ int   g_mask_mode;                 // 0=uint8, 1=float32, 2=int32

// ---------------- mask dtype detection ----------------
__global__ void detect_mask_kernel(const unsigned char* __restrict__ m) {
    __shared__ int c1, c2;
    if (threadIdx.x == 0) { c1 = 0; c2 = 0; }
    __syncthreads();
    int l1 = 0, l2 = 0;
    for (int i = threadIdx.x; i < 16384; i += blockDim.x) {
        if (m[4 * i + 1]) l1++;
        if (m[4 * i + 2] | m[4 * i + 3]) l2++;
    }
    atomicAdd(&c1, l1);
    atomicAdd(&c2, l2);
    __syncthreads();
    if (threadIdx.x == 0) {
        // uint8 bool: nonzero bytes at all offsets; float32 1.0f: bytes 2,3 nonzero, byte1 zero;
        // int32 0/1: bytes 1..3 all zero.
        g_mask_mode = (c1 > 0) ? 0 : ((c2 > 0) ? 1 : 2);
    }
}

// ---------------- prep: build GEMM-ready weights, zero state ----------------
__global__ void prep_kernel(const float* __restrict__ Wc, const void* __restrict__ maskv,
                            const float* __restrict__ Whh, const float* __restrict__ Win,
                            const float* __restrict__ bin, const float* __restrict__ bhh) {
    const int mode = g_mask_mode;
    const unsigned char* m8 = (const unsigned char*)maskv;
    const float*         mf = (const float*)maskv;
    const int*           mi = (const int*)maskv;
    const size_t stride = (size_t)blockDim.x * gridDim.x;
    const size_t t0 = (size_t)blockIdx.x * blockDim.x + threadIdx.x;

    // CW1[(j*NH+h), (i*NH+o)] = mask ? W_comm[j,i,h,o] * 0.1 : 0
    for (size_t idx = t0; idx < (size_t)AH * AH; idx += stride) {
        int col = (int)(idx & (AH - 1));
        int row = (int)(idx >> 11);
        int j = row >> 9, h = row & (NH - 1);
        int i = col >> 9, o = col & (NH - 1);
        size_t widx = (((size_t)j * NA + i) * NH + h) * NH + o;
        bool msk = (mode == 0) ? (m8[widx] != 0)
                 : (mode == 1) ? (mf[widx] != 0.0f)
                               : (mi[widx] != 0);
        g_CW1[idx] = msk ? Wc[widx] * 0.1f : 0.0f;
    }
    // CW2[a][k][o]: k<NH -> W_hh[a,o,k]; else -> W_in[a,o,k-NH]
    for (size_t idx = t0; idx < (size_t)NA * K2 * NH; idx += stride) {
        int o = (int)(idx & (NH - 1));
        int r = (int)(idx >> 9);
        int k = r % K2;
        int a = r / K2;
        g_CW2[idx] = (k < NH) ? Whh[((size_t)a * NH + o) * NH + k]
                              : Win[((size_t)a * NH + o) * NIN + (k - NH)];
    }
    for (size_t idx = t0; idx < (size_t)AH; idx += stride)
        g_bias[idx] = bin[idx] + bhh[idx];
    for (size_t idx = t0; idx < (size_t)B_ * AH; idx += stride)
        g_h[idx] = 0.0f;
}

// ---------------- GEMM tiles: BM=128, BN=64, BK=16, 256 threads, 8x4/thread ----------------
#define BM 128
#define BN 64
#define BK 16

// comm GEMM: C(512 x 2048) = g_h(512 x 2048) @ g_CW1(2048 x 2048)
// epilogue: write comm directly to connections slice as conn[i, b, o]
__global__ __launch_bounds__(256) void comm_gemm_kernel(float* __restrict__ conn) {
    __shared__ float As[2][BK][BM + 4];
    __shared__ float Bs[2][BK][BN];

    const int tid = threadIdx.x;
    const int mBase = blockIdx.y * BM;
    const int nBase = blockIdx.x * BN;
    const int tx = tid & 15, ty = tid >> 4;
    const int m0 = ty * 8, n0 = tx * 4;
    const int arow = tid >> 1;
    const int ak = (tid & 1) * 8;
    const int bk = tid >> 4;
    const int bn = (tid & 15) * 4;

    const float* __restrict__ A = g_h;
    const float* __restrict__ Bm = g_CW1;

    float acc[8][4];
#pragma unroll
    for (int i = 0; i < 8; i++)
#pragma unroll
        for (int j = 0; j < 4; j++) acc[i][j] = 0.0f;

    const float* aRow = A + (size_t)(mBase + arow) * AH;

    // preload tile 0
    {
        float4 a0 = *(const float4*)(aRow + ak);
        float4 a1 = *(const float4*)(aRow + ak + 4);
        float4 b0 = *(const float4*)(Bm + (size_t)bk * AH + nBase + bn);
        As[0][ak + 0][arow] = a0.x; As[0][ak + 1][arow] = a0.y;
        As[0][ak + 2][arow] = a0.z; As[0][ak + 3][arow] = a0.w;
        As[0][ak + 4][arow] = a1.x; As[0][ak + 5][arow] = a1.y;
        As[0][ak + 6][arow] = a1.z; As[0][ak + 7][arow] = a1.w;
        *(float4*)&Bs[0][bk][bn] = b0;
    }
    __syncthreads();

    const int NKT = AH / BK;  // 128

#define COMPUTE_TILE(CUR)                                            \
    _Pragma("unroll")                                                \
    for (int k = 0; k < BK; k++) {                                   \
        float av[8], bv[4];                                          \
        _Pragma("unroll")                                            \
        for (int i2 = 0; i2 < 8; i2++) av[i2] = As[CUR][k][m0 + i2]; \
        _Pragma("unroll")                                            \
        for (int j2 = 0; j2 < 4; j2++) bv[j2] = Bs[CUR][k][n0 + j2]; \
        _Pragma("unroll")                                            \
        for (int i2 = 0; i2 < 8; i2++)                               \
            _Pragma("unroll")                                        \
            for (int j2 = 0; j2 < 4; j2++)                           \
                acc[i2][j2] += av[i2] * bv[j2];                      \
    }

#pragma unroll 2
    for (int kt = 0; kt < NKT - 1; kt++) {
        const int cur = kt & 1, nxt = cur ^ 1;
        const int kb = (kt + 1) * BK;
        float4 na0 = *(const float4*)(aRow + kb + ak);
        float4 na1 = *(const float4*)(aRow + kb + ak + 4);
        float4 nb0 = *(const float4*)(Bm + (size_t)(kb + bk) * AH + nBase + bn);
        COMPUTE_TILE(cur);
        As[nxt][ak + 0][arow] = na0.x; As[nxt][ak + 1][arow] = na0.y;
        As[nxt][ak + 2][arow] = na0.z; As[nxt][ak + 3][arow] = na0.w;
        As[nxt][ak + 4][arow] = na1.x; As[nxt][ak + 5][arow] = na1.y;
        As[nxt][ak + 6][arow] = na1.z; As[nxt][ak + 7][arow] = na1.w;
        *(float4*)&Bs[nxt][bk][bn] = nb0;
        __syncthreads();
    }
    {
        const int cur = (NKT - 1) & 1;
        COMPUTE_TILE(cur);
    }

    // epilogue: conn[agent, b, o]
    const int agent = nBase >> 9;
    const int oBase = (nBase & (NH - 1)) + n0;
    float* dst = conn + ((size_t)agent * B_ + mBase + m0) * NH + oBase;
#pragma unroll
    for (int i2 = 0; i2 < 8; i2++) {
        float4 v;
        v.x = acc[i2][0]; v.y = acc[i2][1]; v.z = acc[i2][2]; v.w = acc[i2][3];
        *(float4*)(dst + (size_t)i2 * NH) = v;
    }
}

// cell GEMM: per agent a: pre(512 x 512) = [h_a | x_t](512 x 640) @ CW2_a(640 x 512)
//            + bias + comm; h_new = tanh(pre) -> g_h
__global__ __launch_bounds__(256) void cell_gemm_kernel(const float* __restrict__ xt,
                                                        const float* __restrict__ connPrev,
                                                        int hasComm) {
    __shared__ float As[2][BK][BM + 4];
    __shared__ float Bs[2][BK][BN];

    const int tid = threadIdx.x;
    const int a = blockIdx.z;
    const int mBase = blockIdx.y * BM;
    const int nBase = blockIdx.x * BN;
    const int tx = tid & 15, ty = tid >> 4;
    const int m0 = ty * 8, n0 = tx * 4;
    const int arow = tid >> 1;
    const int ak = (tid & 1) * 8;
    const int bk = tid >> 4;
    const int bn = (tid & 15) * 4;

    const float* __restrict__ Bm = g_CW2 + (size_t)a * K2 * NH;

    float acc[8][4];
#pragma unroll
    for (int i = 0; i < 8; i++)
#pragma unroll
        for (int j = 0; j < 4; j++) acc[i][j] = 0.0f;

    const int row = mBase + arow;
    const float* hRow = g_h + (size_t)row * AH + a * NH;   // k < NH
    const float* xRow = xt + (size_t)row * NIN - NH;       // k >= NH (offset by -NH)

    {
        const float* p = hRow;  // k0 = ak < NH always at tile 0
        float4 a0 = *(const float4*)(p + ak);
        float4 a1 = *(const float4*)(p + ak + 4);
        float4 b0 = *(const float4*)(Bm + (size_t)bk * NH + nBase + bn);
        As[0][ak + 0][arow] = a0.x; As[0][ak + 1][arow] = a0.y;
        As[0][ak + 2][arow] = a0.z; As[0][ak + 3][arow] = a0.w;
        As[0][ak + 4][arow] = a1.x; As[0][ak + 5][arow] = a1.y;
        As[0][ak + 6][arow] = a1.z; As[0][ak + 7][arow] = a1.w;
        *(float4*)&Bs[0][bk][bn] = b0;
    }
    __syncthreads();

    const int NKT = K2 / BK;  // 40

#pragma unroll 2
    for (int kt = 0; kt < NKT - 1; kt++) {
        const int cur = kt & 1, nxt = cur ^ 1;
        const int kb = (kt + 1) * BK;
        const int k0 = kb + ak;
        const float* p = (k0 < NH) ? (hRow + k0) : (xRow + k0);
        float4 na0 = *(const float4*)(p);
        float4 na1 = *(const float4*)(p + 4);
        float4 nb0 = *(const float4*)(Bm + (size_t)(kb + bk) * NH + nBase + bn);
        COMPUTE_TILE(cur);
        As[nxt][ak + 0][arow] = na0.x; As[nxt][ak + 1][arow] = na0.y;
        As[nxt][ak + 2][arow] = na0.z; As[nxt][ak + 3][arow] = na0.w;
        As[nxt][ak + 4][arow] = na1.x; As[nxt][ak + 5][arow] = na1.y;
        As[nxt][ak + 6][arow] = na1.z; As[nxt][ak + 7][arow] = na1.w;
        *(float4*)&Bs[nxt][bk][bn] = nb0;
        __syncthreads();
    }
    {
        const int cur = (NKT - 1) & 1;
        COMPUTE_TILE(cur);
    }

    const float4 bias4 = *(const float4*)(g_bias + a * NH + nBase + n0);
#pragma unroll
    for (int i2 = 0; i2 < 8; i2++) {
        const int b = mBase + m0 + i2;
        float4 c;
        c.x = acc[i2][0] + bias4.x;
        c.y = acc[i2][1] + bias4.y;
        c.z = acc[i2][2] + bias4.z;
        c.w = acc[i2][3] + bias4.w;
        if (hasComm) {
            float4 cm = *(const float4*)(connPrev + ((size_t)a * B_ + b) * NH + nBase + n0);
            c.x += cm.x; c.y += cm.y; c.z += cm.z; c.w += cm.w;
        }
        c.x = tanhf(c.x); c.y = tanhf(c.y); c.z = tanhf(c.z); c.w = tanhf(c.w);
        *(float4*)(g_h + (size_t)b * AH + a * NH + nBase + n0) = c;
    }
}

// readout: out[b, n] = g_h[b, :] . W_ro[n, :] + b_ro[n]
__global__ __launch_bounds__(256) void readout_kernel(const float* __restrict__ Wro,
                                                      const float* __restrict__ bro,
                                                      float* __restrict__ out) {
    extern __shared__ float sW[];  // NOUT * AH = 80 KB
    for (int i = threadIdx.x; i < NOUT * AH; i += blockDim.x) sW[i] = Wro[i];
    __syncthreads();
    const int warp = threadIdx.x >> 5;
    const int lane = threadIdx.x & 31;
    for (int bb = 0; bb < 4; bb++) {
        const int b = blockIdx.x * 32 + warp * 4 + bb;
        const float* hrow = g_h + (size_t)b * AH;
        float accn[NOUT];
#pragma unroll
        for (int n = 0; n < NOUT; n++) accn[n] = 0.0f;
        for (int k = lane; k < AH; k += 32) {
            const float hv = hrow[k];
#pragma unroll
            for (int n = 0; n < NOUT; n++) accn[n] += hv * sW[n * AH + k];
        }
#pragma unroll
        for (int n = 0; n < NOUT; n++) {
#pragma unroll
            for (int off = 16; off > 0; off >>= 1)
                accn[n] += __shfl_xor_sync(0xFFFFFFFFu, accn[n], off);
            if (lane == 0) out[(size_t)b * NOUT + n] = accn[n] + bro[n];
        }
    }
}

// h_final: (a, b, o) <- g_h[b, a*NH+o]
__global__ void final_copy_kernel(float* __restrict__ hf) {
    const size_t stride = (size_t)blockDim.x * gridDim.x;
    for (size_t idx = (size_t)blockIdx.x * blockDim.x + threadIdx.x;
         idx < (size_t)NA * B_ * NH; idx += stride) {
        int o = (int)(idx & (NH - 1));
        int b = (int)((idx >> 9) & (B_ - 1));
        int a = (int)(idx >> 18);
        hf[idx] = g_h[(size_t)b * AH + a * NH + o];
    }
}

// ---------------- launch ----------------
extern "C" void kernel_launch(void* const* d_in, const int* in_sizes, int n_in,
                              void* d_out, int out_size) {
    const float* x   = (const float*)d_in[0];
    const float* Win = (const float*)d_in[1];
    const float* bin = (const float*)d_in[2];
    const float* Whh = (const float*)d_in[3];
    const float* bhh = (const float*)d_in[4];
    const float* Wc  = (const float*)d_in[5];
    const float* Wro = (const float*)d_in[6];
    const float* bro = (const float*)d_in[7];
    const void*  msk = d_in[8];

    float* out       = (float*)d_out;
    float* out_y     = out;                                          // (T, B, NOUT)
    float* out_hf    = out + (size_t)TSTEPS * B_ * NOUT;             // (NA, B, NH)
    float* out_conn  = out_hf + (size_t)NA * B_ * NH;                // (T-1, NA, B, NH)

    cudaFuncSetAttribute(readout_kernel, cudaFuncAttributeMaxDynamicSharedMemorySize,
                         NOUT * AH * (int)sizeof(float));

    detect_mask_kernel<<<1, 256>>>((const unsigned char*)msk);
    prep_kernel<<<1024, 256>>>(Wc, msk, Whh, Win, bin, bhh);

    for (int t = 0; t < TSTEPS; t++) {
        float* connT = out_conn + (size_t)(t - 1) * NA * B_ * NH;
        if (t >= 1) comm_gemm_kernel<<<dim3(AH / BN, B_ / BM), 256>>>(connT);
        cell_gemm_kernel<<<dim3(NH / BN, B_ / BM, NA), 256>>>(
            x + (size_t)t * B_ * NIN, (t >= 1) ? connT : nullptr, (t >= 1) ? 1 : 0);
        readout_kernel<<<16, 256, NOUT * AH * sizeof(float)>>>(
            Wro, bro, out_y + (size_t)t * B_ * NOUT);
    }
    final_copy_kernel<<<512, 256>>>(out_hf);
}

// round 2
// speedup vs baseline: 1.1811x; 1.1811x over previous
#include <cuda_runtime.h>
#include <cstdint>
#include <cstddef>

#define TSTEPS 64
#define B_     512
#define NA     4
#define NIN    128
#define NH     512
#define NOUT   10
#define AH     2048      // NA * NH
#define K2     640       // NH + NIN

// ---------------- device scratch (no allocations allowed) ----------------
__device__ float g_CW1[(size_t)AH * AH];      // comm weights: [(j*NH+h), (i*NH+o)], pre-scaled by 0.1
__device__ float g_CW2[NA * K2 * NH];         // per agent: rows 0..511 = W_hh^T, rows 512..639 = W_in^T
__device__ float g_bias[AH];                  // b_in + b_hh, per (a, o)
__device__ float g_h[(size_t)B_ * AH];        // hidden state, layout (b, a*NH+o)
__device__ int   g_mask_mode;                 // 0=uint8, 1=float32, 2=int32

// ---------------- mask dtype detection ----------------
__global__ void detect_mask_kernel(const unsigned char* __restrict__ m) {
    __shared__ int c1, c2;
    if (threadIdx.x == 0) { c1 = 0; c2 = 0; }
    __syncthreads();
    int l1 = 0, l2 = 0;
    for (int i = threadIdx.x; i < 16384; i += blockDim.x) {
        if (m[4 * i + 1]) l1++;
        if (m[4 * i + 2] | m[4 * i + 3]) l2++;
    }
    atomicAdd(&c1, l1);
    atomicAdd(&c2, l2);
    __syncthreads();
    if (threadIdx.x == 0) {
        g_mask_mode = (c1 > 0) ? 0 : ((c2 > 0) ? 1 : 2);
    }
}

// ---------------- prep: build GEMM-ready weights, zero state ----------------
__global__ void prep_kernel(const float* __restrict__ Wc, const void* __restrict__ maskv,
                            const float* __restrict__ Whh, const float* __restrict__ Win,
                            const float* __restrict__ bin, const float* __restrict__ bhh) {
    const int mode = g_mask_mode;
    const unsigned char* m8 = (const unsigned char*)maskv;
    const float*         mf = (const float*)maskv;
    const int*           mi = (const int*)maskv;
    const size_t stride = (size_t)blockDim.x * gridDim.x;
    const size_t t0 = (size_t)blockIdx.x * blockDim.x + threadIdx.x;

    for (size_t idx = t0; idx < (size_t)AH * AH; idx += stride) {
        int col = (int)(idx & (AH - 1));
        int row = (int)(idx >> 11);
        int j = row >> 9, h = row & (NH - 1);
        int i = col >> 9, o = col & (NH - 1);
        size_t widx = (((size_t)j * NA + i) * NH + h) * NH + o;
        bool msk = (mode == 0) ? (m8[widx] != 0)
                 : (mode == 1) ? (mf[widx] != 0.0f)
                               : (mi[widx] != 0);
        g_CW1[idx] = msk ? Wc[widx] * 0.1f : 0.0f;
    }
    for (size_t idx = t0; idx < (size_t)NA * K2 * NH; idx += stride) {
        int o = (int)(idx & (NH - 1));
        int r = (int)(idx >> 9);
        int k = r % K2;
        int a = r / K2;
        g_CW2[idx] = (k < NH) ? Whh[((size_t)a * NH + o) * NH + k]
                              : Win[((size_t)a * NH + o) * NIN + (k - NH)];
    }
    for (size_t idx = t0; idx < (size_t)AH; idx += stride)
        g_bias[idx] = bin[idx] + bhh[idx];
    for (size_t idx = t0; idx < (size_t)B_ * AH; idx += stride)
        g_h[idx] = 0.0f;
}

// ---------------- GEMM tiles: BM=128, BN=64, BK=16, 256 threads, 8x4/thread ----------------
#define BM 128
#define BN 64
#define BK 16
#define BNP 68   // padded Bs row (floats) to kill the 2-way LDS conflict

// comm GEMM: C(512 x 2048) = g_h(512 x 2048) @ g_CW1(2048 x 2048)
__global__ __launch_bounds__(256) void comm_gemm_kernel(float* __restrict__ conn) {
    __shared__ float As[2][BK][BM + 4];
    __shared__ float Bs[2][BK][BNP];

    const int tid = threadIdx.x;
    const int mBase = blockIdx.y * BM;
    const int nBase = blockIdx.x * BN;
    const int tx = tid & 15, ty = tid >> 4;
    const int m0 = ty * 8, n0 = tx * 4;
    const int arow = tid >> 1;
    const int ak = (tid & 1) * 8;
    const int bk = tid >> 4;
    const int bn = (tid & 15) * 4;

    const float* __restrict__ A = g_h;
    const float* __restrict__ Bm = g_CW1;

    float acc[8][4];
#pragma unroll
    for (int i = 0; i < 8; i++)
#pragma unroll
        for (int j = 0; j < 4; j++) acc[i][j] = 0.0f;

    const float* aRow = A + (size_t)(mBase + arow) * AH;

    {
        float4 a0 = *(const float4*)(aRow + ak);
        float4 a1 = *(const float4*)(aRow + ak + 4);
        float4 b0 = *(const float4*)(Bm + (size_t)bk * AH + nBase + bn);
        As[0][ak + 0][arow] = a0.x; As[0][ak + 1][arow] = a0.y;
        As[0][ak + 2][arow] = a0.z; As[0][ak + 3][arow] = a0.w;
        As[0][ak + 4][arow] = a1.x; As[0][ak + 5][arow] = a1.y;
        As[0][ak + 6][arow] = a1.z; As[0][ak + 7][arow] = a1.w;
        *(float4*)&Bs[0][bk][bn] = b0;
    }
    __syncthreads();

    const int NKT = AH / BK;  // 128

#define COMPUTE_TILE(CUR)                                            \
    _Pragma("unroll")                                                \
    for (int k = 0; k < BK; k++) {                                   \
        float av[8], bv[4];                                          \
        _Pragma("unroll")                                            \
        for (int i2 = 0; i2 < 8; i2++) av[i2] = As[CUR][k][m0 + i2]; \
        _Pragma("unroll")                                            \
        for (int j2 = 0; j2 < 4; j2++) bv[j2] = Bs[CUR][k][n0 + j2]; \
        _Pragma("unroll")                                            \
        for (int i2 = 0; i2 < 8; i2++)                               \
            _Pragma("unroll")                                        \
            for (int j2 = 0; j2 < 4; j2++)                           \
                acc[i2][j2] += av[i2] * bv[j2];                      \
    }

#pragma unroll 2
    for (int kt = 0; kt < NKT - 1; kt++) {
        const int cur = kt & 1, nxt = cur ^ 1;
        const int kb = (kt + 1) * BK;
        float4 na0 = *(const float4*)(aRow + kb + ak);
        float4 na1 = *(const float4*)(aRow + kb + ak + 4);
        float4 nb0 = *(const float4*)(Bm + (size_t)(kb + bk) * AH + nBase + bn);
        COMPUTE_TILE(cur);
        As[nxt][ak + 0][arow] = na0.x; As[nxt][ak + 1][arow] = na0.y;
        As[nxt][ak + 2][arow] = na0.z; As[nxt][ak + 3][arow] = na0.w;
        As[nxt][ak + 4][arow] = na1.x; As[nxt][ak + 5][arow] = na1.y;
        As[nxt][ak + 6][arow] = na1.z; As[nxt][ak + 7][arow] = na1.w;
        *(float4*)&Bs[nxt][bk][bn] = nb0;
        __syncthreads();
    }
    {
        const int cur = (NKT - 1) & 1;
        COMPUTE_TILE(cur);
    }

    const int agent = nBase >> 9;
    const int oBase = (nBase & (NH - 1)) + n0;
    float* dst = conn + ((size_t)agent * B_ + mBase + m0) * NH + oBase;
#pragma unroll
    for (int i2 = 0; i2 < 8; i2++) {
        float4 v;
        v.x = acc[i2][0]; v.y = acc[i2][1]; v.z = acc[i2][2]; v.w = acc[i2][3];
        *(float4*)(dst + (size_t)i2 * NH) = v;
    }
}

// cell GEMM: per agent a: pre(512 x 512) = [h_a | x_t](512 x 640) @ CW2_a(640 x 512)
__global__ __launch_bounds__(256) void cell_gemm_kernel(const float* __restrict__ xt,
                                                        const float* __restrict__ connPrev,
                                                        int hasComm) {
    __shared__ float As[2][BK][BM + 4];
    __shared__ float Bs[2][BK][BNP];

    const int tid = threadIdx.x;
    const int a = blockIdx.z;
    const int mBase = blockIdx.y * BM;
    const int nBase = blockIdx.x * BN;
    const int tx = tid & 15, ty = tid >> 4;
    const int m0 = ty * 8, n0 = tx * 4;
    const int arow = tid >> 1;
    const int ak = (tid & 1) * 8;
    const int bk = tid >> 4;
    const int bn = (tid & 15) * 4;

    const float* __restrict__ Bm = g_CW2 + (size_t)a * K2 * NH;

    float acc[8][4];
#pragma unroll
    for (int i = 0; i < 8; i++)
#pragma unroll
        for (int j = 0; j < 4; j++) acc[i][j] = 0.0f;

    const int row = mBase + arow;
    const float* hRow = g_h + (size_t)row * AH + a * NH;
    const float* xRow = xt + (size_t)row * NIN - NH;

    {
        const float* p = hRow;
        float4 a0 = *(const float4*)(p + ak);
        float4 a1 = *(const float4*)(p + ak + 4);
        float4 b0 = *(const float4*)(Bm + (size_t)bk * NH + nBase + bn);
        As[0][ak + 0][arow] = a0.x; As[0][ak + 1][arow] = a0.y;
        As[0][ak + 2][arow] = a0.z; As[0][ak + 3][arow] = a0.w;
        As[0][ak + 4][arow] = a1.x; As[0][ak + 5][arow] = a1.y;
        As[0][ak + 6][arow] = a1.z; As[0][ak + 7][arow] = a1.w;
        *(float4*)&Bs[0][bk][bn] = b0;
    }
    __syncthreads();

    const int NKT = K2 / BK;  // 40

#pragma unroll 2
    for (int kt = 0; kt < NKT - 1; kt++) {
        const int cur = kt & 1, nxt = cur ^ 1;
        const int kb = (kt + 1) * BK;
        const int k0 = kb + ak;
        const float* p = (k0 < NH) ? (hRow + k0) : (xRow + k0);
        float4 na0 = *(const float4*)(p);
        float4 na1 = *(const float4*)(p + 4);
        float4 nb0 = *(const float4*)(Bm + (size_t)(kb + bk) * NH + nBase + bn);
        COMPUTE_TILE(cur);
        As[nxt][ak + 0][arow] = na0.x; As[nxt][ak + 1][arow] = na0.y;
        As[nxt][ak + 2][arow] = na0.z; As[nxt][ak + 3][arow] = na0.w;
        As[nxt][ak + 4][arow] = na1.x; As[nxt][ak + 5][arow] = na1.y;
        As[nxt][ak + 6][arow] = na1.z; As[nxt][ak + 7][arow] = na1.w;
        *(float4*)&Bs[nxt][bk][bn] = nb0;
        __syncthreads();
    }
    {
        const int cur = (NKT - 1) & 1;
        COMPUTE_TILE(cur);
    }

    const float4 bias4 = *(const float4*)(g_bias + a * NH + nBase + n0);
#pragma unroll
    for (int i2 = 0; i2 < 8; i2++) {
        const int b = mBase + m0 + i2;
        float4 c;
        c.x = acc[i2][0] + bias4.x;
        c.y = acc[i2][1] + bias4.y;
        c.z = acc[i2][2] + bias4.z;
        c.w = acc[i2][3] + bias4.w;
        if (hasComm) {
            float4 cm = *(const float4*)(connPrev + ((size_t)a * B_ + b) * NH + nBase + n0);
            c.x += cm.x; c.y += cm.y; c.z += cm.z; c.w += cm.w;
        }
        c.x = tanhf(c.x); c.y = tanhf(c.y); c.z = tanhf(c.z); c.w = tanhf(c.w);
        *(float4*)(g_h + (size_t)b * AH + a * NH + nBase + n0) = c;
    }
}

// readout: out(512x10) = g_h(512x2048) @ W_ro^T + b_ro
// 64 blocks x 8 warps; one warp per batch row; float4 k-loop; W_ro hits L1/L2.
__global__ __launch_bounds__(256) void readout_kernel(const float* __restrict__ Wro,
                                                      const float* __restrict__ bro,
                                                      float* __restrict__ out) {
    const int warp = threadIdx.x >> 5;
    const int lane = threadIdx.x & 31;
    const int b = blockIdx.x * 8 + warp;
    const float* hrow = g_h + (size_t)b * AH;

    float accn[NOUT];
#pragma unroll
    for (int n = 0; n < NOUT; n++) accn[n] = 0.0f;

#pragma unroll
    for (int it = 0; it < AH / 128; it++) {   // 16 iters: 32 lanes * 4 floats
        const int k = it * 128 + lane * 4;
        const float4 h4 = *(const float4*)(hrow + k);
#pragma unroll
        for (int n = 0; n < NOUT; n++) {
            const float4 w4 = __ldg((const float4*)(Wro + (size_t)n * AH + k));
            accn[n] += h4.x * w4.x + h4.y * w4.y + h4.z * w4.z + h4.w * w4.w;
        }
    }
#pragma unroll
    for (int n = 0; n < NOUT; n++) {
#pragma unroll
        for (int off = 16; off > 0; off >>= 1)
            accn[n] += __shfl_xor_sync(0xFFFFFFFFu, accn[n], off);
    }
    if (lane < NOUT) out[(size_t)b * NOUT + lane] = accn[lane] + bro[lane];
}

// h_final: (a, b, o) <- g_h[b, a*NH+o]
__global__ void final_copy_kernel(float* __restrict__ hf) {
    const size_t stride = (size_t)blockDim.x * gridDim.x;
    for (size_t idx = (size_t)blockIdx.x * blockDim.x + threadIdx.x;
         idx < (size_t)NA * B_ * NH; idx += stride) {
        int o = (int)(idx & (NH - 1));
        int b = (int)((idx >> 9) & (B_ - 1));
        int a = (int)(idx >> 18);
        hf[idx] = g_h[(size_t)b * AH + a * NH + o];
    }
}

// ---------------- launch ----------------
extern "C" void kernel_launch(void* const* d_in, const int* in_sizes, int n_in,
                              void* d_out, int out_size) {
    const float* x   = (const float*)d_in[0];
    const float* Win = (const float*)d_in[1];
    const float* bin = (const float*)d_in[2];
    const float* Whh = (const float*)d_in[3];
    const float* bhh = (const float*)d_in[4];
    const float* Wc  = (const float*)d_in[5];
    const float* Wro = (const float*)d_in[6];
    const float* bro = (const float*)d_in[7];
    const void*  msk = d_in[8];

    float* out       = (float*)d_out;
    float* out_y     = out;
    float* out_hf    = out + (size_t)TSTEPS * B_ * NOUT;
    float* out_conn  = out_hf + (size_t)NA * B_ * NH;

    detect_mask_kernel<<<1, 256>>>((const unsigned char*)msk);
    prep_kernel<<<1024, 256>>>(Wc, msk, Whh, Win, bin, bhh);

    for (int t = 0; t < TSTEPS; t++) {
        float* connT = out_conn + (size_t)(t - 1) * NA * B_ * NH;
        if (t >= 1) comm_gemm_kernel<<<dim3(AH / BN, B_ / BM), 256>>>(connT);
        cell_gemm_kernel<<<dim3(NH / BN, B_ / BM, NA), 256>>>(
            x + (size_t)t * B_ * NIN, (t >= 1) ? connT : nullptr, (t >= 1) ? 1 : 0);
        readout_kernel<<<B_ / 8, 256>>>(Wro, bro, out_y + (size_t)t * B_ * NOUT);
    }
    final_copy_kernel<<<512, 256>>>(out_hf);
}

// round 5
// speedup vs baseline: 2.0812x; 1.7620x over previous
#include <cuda_runtime.h>
#include <cuda_bf16.h>
#include <cstdint>
#include <cstddef>

#define TSTEPS 64
#define B_     512
#define NA     4
#define NIN    128
#define NH     512
#define NOUT   10
#define AH     2048      // NA * NH
#define K3C    6144      // comm K: [hi(2048)|lo(2048)|hi(2048)]
#define K3L    1920      // cell K: [h_hi 512|x_hi 128|h_lo 512|x_lo 128|h_hi 512|x_hi 128]

// ---------------- device scratch ----------------
__device__ __align__(1024) __nv_bfloat16 g_CWb1[(size_t)AH * K3C];       // comm B': [n=i*512+o][k]
__device__ __align__(1024) __nv_bfloat16 g_CWb2[(size_t)NA * NH * K3L];  // cell per agent: [o][k]
__device__ __align__(1024) __nv_bfloat16 g_xs[(size_t)TSTEPS * B_ * 256];// x split: [t][b][hi|lo]
__device__ __align__(1024) __nv_bfloat16 g_hA[(size_t)B_ * K3C];         // h split A': [b][hi|lo|hi]
__device__ __align__(1024) float g_h[(size_t)B_ * AH];                   // f32 h
__device__ __align__(1024) float g_bias[AH];
__device__ int   g_mask_mode;

// ---------------- helpers ----------------
__device__ __forceinline__ uint32_t smem_u32(const void* p) {
    uint32_t a;
    asm("{ .reg .u64 t; cvta.to.shared.u64 t, %1; cvt.u32.u64 %0, t; }" : "=r"(a) : "l"(p));
    return a;
}
#define SWZ(x) ((x) ^ (((x) >> 3) & 0x70))

__device__ __forceinline__ void cp16(uint32_t dst, const void* src) {
    asm volatile("cp.async.cg.shared.global [%0], [%1], 16;" :: "r"(dst), "l"(src));
}
#define CP_COMMIT() asm volatile("cp.async.commit_group;" ::: "memory")
#define CP_WAIT2()  asm volatile("cp.async.wait_group 2;" ::: "memory")
#define CP_WAIT0()  asm volatile("cp.async.wait_group 0;" ::: "memory")

__device__ __forceinline__ void ldm_x4(uint32_t addr, uint32_t& r0, uint32_t& r1,
                                       uint32_t& r2, uint32_t& r3) {
    asm volatile("ldmatrix.sync.aligned.m8n8.x4.shared.b16 {%0,%1,%2,%3}, [%4];"
                 : "=r"(r0), "=r"(r1), "=r"(r2), "=r"(r3) : "r"(addr));
}
__device__ __forceinline__ void mma16816(float* c, const uint32_t* a, uint32_t b0, uint32_t b1) {
    asm volatile("mma.sync.aligned.m16n8k16.row.col.f32.bf16.bf16.f32 "
                 "{%0,%1,%2,%3}, {%4,%5,%6,%7}, {%8,%9}, {%0,%1,%2,%3};"
                 : "+f"(c[0]), "+f"(c[1]), "+f"(c[2]), "+f"(c[3])
                 : "r"(a[0]), "r"(a[1]), "r"(a[2]), "r"(a[3]), "r"(b0), "r"(b1));
}

// ---------------- mask dtype detection ----------------
__global__ void detect_mask_kernel(const unsigned char* __restrict__ m) {
    __shared__ int c1, c2;
    if (threadIdx.x == 0) { c1 = 0; c2 = 0; }
    __syncthreads();
    int l1 = 0, l2 = 0;
    for (int i = threadIdx.x; i < 16384; i += blockDim.x) {
        if (m[4 * i + 1]) l1++;
        if (m[4 * i + 2] | m[4 * i + 3]) l2++;
    }
    atomicAdd(&c1, l1);
    atomicAdd(&c2, l2);
    __syncthreads();
    if (threadIdx.x == 0) g_mask_mode = (c1 > 0) ? 0 : ((c2 > 0) ? 1 : 2);
}

// ---------------- prep ----------------
__global__ void prep_kernel(const float* __restrict__ x,
                            const float* __restrict__ Wc, const void* __restrict__ maskv,
                            const float* __restrict__ Whh, const float* __restrict__ Win,
                            const float* __restrict__ bin, const float* __restrict__ bhh) {
    const int mode = g_mask_mode;
    const unsigned char* m8 = (const unsigned char*)maskv;
    const float*         mf = (const float*)maskv;
    const int*           mi = (const int*)maskv;
    const size_t stride = (size_t)blockDim.x * gridDim.x;
    const size_t t0 = (size_t)blockIdx.x * blockDim.x + threadIdx.x;

    for (size_t idx = t0; idx < (size_t)AH * 2048; idx += stride) {
        int k0 = (int)(idx & 2047);
        int n = (int)(idx >> 11);
        int i = n >> 9, o = n & (NH - 1);
        int j = k0 >> 9, h = k0 & (NH - 1);
        size_t widx = (((size_t)j * NA + i) * NH + h) * NH + o;
        bool msk = (mode == 0) ? (m8[widx] != 0)
                 : (mode == 1) ? (mf[widx] != 0.0f)
                               : (mi[widx] != 0);
        float w = msk ? Wc[widx] * 0.1f : 0.0f;
        __nv_bfloat16 hi = __float2bfloat16(w);
        __nv_bfloat16 lo = __float2bfloat16(w - __bfloat162float(hi));
        __nv_bfloat16* row = g_CWb1 + (size_t)n * K3C;
        row[k0] = hi; row[2048 + k0] = hi; row[4096 + k0] = lo;
    }
    for (size_t idx = t0; idx < (size_t)NA * NH * NH; idx += stride) {
        int k = (int)(idx & (NH - 1));
        int r = (int)(idx >> 9);
        int o = r & (NH - 1);
        int a = r >> 9;
        float w = Whh[idx];
        __nv_bfloat16 hi = __float2bfloat16(w);
        __nv_bfloat16 lo = __float2bfloat16(w - __bfloat162float(hi));
        __nv_bfloat16* row = g_CWb2 + ((size_t)a * NH + o) * K3L;
        row[k] = hi; row[640 + k] = hi; row[1280 + k] = lo;
    }
    for (size_t idx = t0; idx < (size_t)NA * NH * NIN; idx += stride) {
        int k = (int)(idx & (NIN - 1));
        int r = (int)(idx >> 7);
        int o = r & (NH - 1);
        int a = r >> 9;
        float w = Win[idx];
        __nv_bfloat16 hi = __float2bfloat16(w);
        __nv_bfloat16 lo = __float2bfloat16(w - __bfloat162float(hi));
        __nv_bfloat16* row = g_CWb2 + ((size_t)a * NH + o) * K3L;
        row[512 + k] = hi; row[1152 + k] = hi; row[1792 + k] = lo;
    }
    for (size_t idx = t0; idx < (size_t)TSTEPS * B_ * NIN; idx += stride) {
        int k = (int)(idx & (NIN - 1));
        size_t tb = idx >> 7;
        float v = x[idx];
        __nv_bfloat16 hi = __float2bfloat16(v);
        __nv_bfloat16 lo = __float2bfloat16(v - __bfloat162float(hi));
        __nv_bfloat16* row = g_xs + tb * 256;
        row[k] = hi; row[128 + k] = lo;
    }
    for (size_t idx = t0; idx < (size_t)AH; idx += stride)
        g_bias[idx] = bin[idx] + bhh[idx];
    for (size_t idx = t0; idx < (size_t)B_ * AH; idx += stride)
        g_h[idx] = 0.0f;
    uint32_t* hA32 = (uint32_t*)g_hA;
    for (size_t idx = t0; idx < (size_t)B_ * K3C / 2; idx += stride)
        hA32[idx] = 0u;
}

// ---------------- HMMA GEMM: BM=64, BN=128, BK=64, 8 warps (warp tile 32x32) ----------------
#define STAGE 24576            // A 8KB + B 16KB
#define SMEM_DYN (4 * STAGE + 1024)

// load one k-chunk of 64: A tile 64x64 bf16 (rows aSeg + (mBase+r)*aStride), B tile 128x64
__device__ __forceinline__ void load_chunk(uint32_t tiles, int s, int tid,
                                           const __nv_bfloat16* aSeg, int aStride,
                                           const __nv_bfloat16* bRow0, int bStride,
                                           int mBase, int nBase, int k0b) {
    uint32_t aAddr = tiles + s * STAGE;
    uint32_t bAddr = aAddr + 8192;
#pragma unroll
    for (int u = 0; u < 2; u++) {
        int i = tid * 2 + u;           // 0..511
        int r = i >> 3, g = i & 7;
        cp16(aAddr + SWZ(r * 128 + g * 16), aSeg + (size_t)(mBase + r) * aStride + g * 8);
    }
#pragma unroll
    for (int u = 0; u < 4; u++) {
        int i = tid * 4 + u;           // 0..1023
        int r = i >> 3, g = i & 7;
        cp16(bAddr + SWZ(r * 128 + g * 16), bRow0 + (size_t)(nBase + r) * bStride + k0b + g * 8);
    }
    CP_COMMIT();
}

__device__ __forceinline__ void compute_chunk(uint32_t aBase, uint32_t bBase,
                                              int wm, int wn, int lane,
                                              float acc[2][4][4]) {
#pragma unroll
    for (int ks = 0; ks < 4; ks++) {
        const int kb = ks * 32 + (lane >> 4) * 16;   // byte col: k0*2 + (lane/16)*16
        uint32_t af[2][4];
#pragma unroll
        for (int mt = 0; mt < 2; mt++) {
            int row = wm + mt * 16 + (lane & 15);
            ldm_x4(aBase + SWZ(row * 128 + kb), af[mt][0], af[mt][1], af[mt][2], af[mt][3]);
        }
        uint32_t bf[4][2];
#pragma unroll
        for (int ng = 0; ng < 2; ng++) {
            int row = wn + ng * 16 + (lane & 15);
            uint32_t r0, r1, r2, r3;
            ldm_x4(bBase + SWZ(row * 128 + kb), r0, r1, r2, r3);
            bf[ng * 2][0] = r0; bf[ng * 2 + 1][0] = r1;
            bf[ng * 2][1] = r2; bf[ng * 2 + 1][1] = r3;
        }
#pragma unroll
        for (int mt = 0; mt < 2; mt++)
#pragma unroll
            for (int nt = 0; nt < 4; nt++)
                mma16816(acc[mt][nt], af[mt], bf[nt][0], bf[nt][1]);
    }
}

// comm: conn(4,512,512) <- g_hA(512 x 6144) @ g_CWb1(2048 x 6144)^T
__global__ __launch_bounds__(256) void comm_gemm_mma(float* __restrict__ conn) {
    extern __shared__ char dsm[];
    uint32_t tiles = (smem_u32(dsm) + 1023) & ~1023u;
    const int tid = threadIdx.x, wid = tid >> 5, lane = tid & 31;
    const int nBase = blockIdx.x * 128;      // over AH
    const int mBase = blockIdx.y * 64;       // over B_
    const int wm = (wid & 1) * 32, wn = (wid >> 1) * 32;

    float acc[2][4][4];
#pragma unroll
    for (int i = 0; i < 2; i++)
#pragma unroll
        for (int j = 0; j < 4; j++)
#pragma unroll
            for (int q = 0; q < 4; q++) acc[i][j][q] = 0.0f;

    const int C = K3C / 64;   // 96
    for (int p = 0; p < 3; p++)
        load_chunk(tiles, p, tid, g_hA + p * 64, K3C, g_CWb1, K3C, mBase, nBase, p * 64);

    for (int c = 0; c < C; c++) {
        const int s = c & 3;
        if (c + 3 < C) CP_WAIT2(); else CP_WAIT0();
        __syncthreads();
        compute_chunk(tiles + s * STAGE, tiles + s * STAGE + 8192, wm, wn, lane, acc);
        const int n = c + 3;
        if (n < C)
            load_chunk(tiles, n & 3, tid, g_hA + n * 64, K3C, g_CWb1, K3C, mBase, nBase, n * 64);
    }

    // epilogue: conn[agent, b, o]
    const int agent = nBase >> 9;
#pragma unroll
    for (int mt = 0; mt < 2; mt++) {
#pragma unroll
        for (int nt = 0; nt < 4; nt++) {
            const int r = mBase + wm + mt * 16 + (lane >> 2);
            const int col = ((nBase & (NH - 1)) + wn + nt * 8 + (lane & 3) * 2);
            float* d0 = conn + ((size_t)agent * B_ + r) * NH + col;
            *(float2*)d0 = make_float2(acc[mt][nt][0], acc[mt][nt][1]);
            float* d1 = conn + ((size_t)agent * B_ + r + 8) * NH + col;
            *(float2*)d1 = make_float2(acc[mt][nt][2], acc[mt][nt][3]);
        }
    }
}

// cell: per agent a: pre(512x512) = A'(512x1920) @ CWb2_a(512x1920)^T + bias + conn; h=tanh
__global__ __launch_bounds__(256) void cell_gemm_mma(int t, const float* __restrict__ connPrev,
                                                     int hasComm) {
    extern __shared__ char dsm[];
    uint32_t tiles = (smem_u32(dsm) + 1023) & ~1023u;
    const int tid = threadIdx.x, wid = tid >> 5, lane = tid & 31;
    const int a = blockIdx.z;
    const int nBase = blockIdx.x * 128;      // over NH (o)
    const int mBase = blockIdx.y * 64;       // over B_ (b)
    const int wm = (wid & 1) * 32, wn = (wid >> 1) * 32;

    const __nv_bfloat16* Brow = g_CWb2 + (size_t)a * NH * K3L;
    const __nv_bfloat16* xsT = g_xs + (size_t)t * B_ * 256;

    auto aseg = [&](int c, const __nv_bfloat16*& seg, int& rs) {
        if (c < 8)       { seg = g_hA + a * NH + c * 64;               rs = K3C; }
        else if (c < 10) { seg = xsT + (c - 8) * 64;                   rs = 256; }
        else if (c < 18) { seg = g_hA + 2048 + a * NH + (c - 10) * 64; rs = K3C; }
        else if (c < 20) { seg = xsT + 128 + (c - 18) * 64;            rs = 256; }
        else if (c < 28) { seg = g_hA + a * NH + (c - 20) * 64;        rs = K3C; }
        else             { seg = xsT + (c - 28) * 64;                  rs = 256; }
    };

    float acc[2][4][4];
#pragma unroll
    for (int i = 0; i < 2; i++)
#pragma unroll
        for (int j = 0; j < 4; j++)
#pragma unroll
            for (int q = 0; q < 4; q++) acc[i][j][q] = 0.0f;

    const int C = K3L / 64;   // 30
    for (int p = 0; p < 3; p++) {
        const __nv_bfloat16* seg; int rs; aseg(p, seg, rs);
        load_chunk(tiles, p, tid, seg, rs, Brow, K3L, mBase, nBase, p * 64);
    }

    for (int c = 0; c < C; c++) {
        const int s = c & 3;
        if (c + 3 < C) CP_WAIT2(); else CP_WAIT0();
        __syncthreads();
        compute_chunk(tiles + s * STAGE, tiles + s * STAGE + 8192, wm, wn, lane, acc);
        const int n = c + 3;
        if (n < C) {
            const __nv_bfloat16* seg; int rs; aseg(n, seg, rs);
            load_chunk(tiles, n & 3, tid, seg, rs, Brow, K3L, mBase, nBase, n * 64);
        }
    }

    // epilogue: bias + comm + tanh; write g_h f32 + g_hA bf16 split [hi|lo|hi]
#pragma unroll
    for (int mt = 0; mt < 2; mt++) {
#pragma unroll
        for (int nt = 0; nt < 4; nt++) {
            const int r0 = mBase + wm + mt * 16 + (lane >> 2);
            const int o = nBase + wn + nt * 8 + (lane & 3) * 2;
            const float2 bias2 = *(const float2*)(g_bias + a * NH + o);
#pragma unroll
            for (int h2 = 0; h2 < 2; h2++) {
                const int b = r0 + h2 * 8;
                float v0 = acc[mt][nt][h2 * 2 + 0] + bias2.x;
                float v1 = acc[mt][nt][h2 * 2 + 1] + bias2.y;
                if (hasComm) {
                    const float2 cm = *(const float2*)(connPrev + ((size_t)a * B_ + b) * NH + o);
                    v0 += cm.x; v1 += cm.y;
                }
                v0 = tanhf(v0); v1 = tanhf(v1);
                *(float2*)(g_h + (size_t)b * AH + a * NH + o) = make_float2(v0, v1);
                __nv_bfloat162 hi2 = __floats2bfloat162_rn(v0, v1);
                __nv_bfloat162 lo2 = __floats2bfloat162_rn(v0 - __bfloat162float(hi2.x),
                                                           v1 - __bfloat162float(hi2.y));
                __nv_bfloat16* hp = g_hA + (size_t)b * K3C + a * NH + o;
                *(__nv_bfloat162*)(hp) = hi2;
                *(__nv_bfloat162*)(hp + 4096) = hi2;
                *(__nv_bfloat162*)(hp + 2048) = lo2;
            }
        }
    }
}

// ---------------- readout: 512 blocks, one batch row each ----------------
__global__ __launch_bounds__(128) void readout_kernel(const float* __restrict__ Wro,
                                                      const float* __restrict__ bro,
                                                      float* __restrict__ out) {
    __shared__ float sred[4][NOUT];
    const int b = blockIdx.x;
    const int tid = threadIdx.x;
    const float* hrow = g_h + (size_t)b * AH;
    float acc[NOUT];
#pragma unroll
    for (int n = 0; n < NOUT; n++) acc[n] = 0.0f;
#pragma unroll
    for (int it = 0; it < 4; it++) {
        const int k = (it * 128 + tid) * 4;
        const float4 h4 = *(const float4*)(hrow + k);
#pragma unroll
        for (int n = 0; n < NOUT; n++) {
            const float4 w4 = __ldg((const float4*)(Wro + (size_t)n * AH + k));
            acc[n] += h4.x * w4.x + h4.y * w4.y + h4.z * w4.z + h4.w * w4.w;
        }
    }
    const int warp = tid >> 5, lane = tid & 31;
#pragma unroll
    for (int n = 0; n < NOUT; n++) {
#pragma unroll
        for (int off = 16; off > 0; off >>= 1)
            acc[n] += __shfl_xor_sync(0xFFFFFFFFu, acc[n], off);
        if (lane == 0) sred[warp][n] = acc[n];
    }
    __syncthreads();
    if (tid < NOUT)
        out[(size_t)b * NOUT + tid] = sred[0][tid] + sred[1][tid] + sred[2][tid] + sred[3][tid] + bro[tid];
}

// ---------------- h_final ----------------
__global__ void final_copy_kernel(float* __restrict__ hf) {
    const size_t stride = (size_t)blockDim.x * gridDim.x;
    for (size_t idx = (size_t)blockIdx.x * blockDim.x + threadIdx.x;
         idx < (size_t)NA * B_ * NH; idx += stride) {
        int o = (int)(idx & (NH - 1));
        int b = (int)((idx >> 9) & (B_ - 1));
        int a = (int)(idx >> 18);
        hf[idx] = g_h[(size_t)b * AH + a * NH + o];
    }
}

// ---------------- launch ----------------
extern "C" void kernel_launch(void* const* d_in, const int* in_sizes, int n_in,
                              void* d_out, int out_size) {
    const float* x   = (const float*)d_in[0];
    const float* Win = (const float*)d_in[1];
    const float* bin = (const float*)d_in[2];
    const float* Whh = (const float*)d_in[3];
    const float* bhh = (const float*)d_in[4];
    const float* Wc  = (const float*)d_in[5];
    const float* Wro = (const float*)d_in[6];
    const float* bro = (const float*)d_in[7];
    const void*  msk = d_in[8];

    float* out       = (float*)d_out;
    float* out_y     = out;
    float* out_hf    = out + (size_t)TSTEPS * B_ * NOUT;
    float* out_conn  = out_hf + (size_t)NA * B_ * NH;

    cudaFuncSetAttribute(comm_gemm_mma, cudaFuncAttributeMaxDynamicSharedMemorySize, SMEM_DYN);
    cudaFuncSetAttribute(cell_gemm_mma, cudaFuncAttributeMaxDynamicSharedMemorySize, SMEM_DYN);

    detect_mask_kernel<<<1, 256>>>((const unsigned char*)msk);
    prep_kernel<<<2048, 256>>>(x, Wc, msk, Whh, Win, bin, bhh);

    for (int t = 0; t < TSTEPS; t++) {
        float* connT = out_conn + (size_t)(t - 1) * NA * B_ * NH;
        if (t >= 1) comm_gemm_mma<<<dim3(AH / 128, B_ / 64), 256, SMEM_DYN>>>(connT);
        cell_gemm_mma<<<dim3(NH / 128, B_ / 64, NA), 256, SMEM_DYN>>>(
            t, (t >= 1) ? connT : nullptr, (t >= 1) ? 1 : 0);
        readout_kernel<<<B_, 128>>>(Wro, bro, out_y + (size_t)t * B_ * NOUT);
    }
    final_copy_kernel<<<512, 256>>>(out_hf);
}

// round 6
// speedup vs baseline: 2.9564x; 1.4205x over previous
#include <cuda_runtime.h>
#include <cuda_bf16.h>
#include <cstdint>
#include <cstddef>

#define TSTEPS 64
#define B_     512
#define NA     4
#define NIN    128
#define NH     512
#define NOUT   10
#define AH     2048      // NA * NH
#define K3C    6144      // h split A' width: [hi(2048)|lo(2048)|hi(2048)]
#define K3CA   4608      // comm per-agent K: 3 * 1536 (j != i only)
#define K3L    1920      // cell K: [h_hi 512|x_hi 128|h_lo 512|x_lo 128|h_hi 512|x_hi 128]

// ---------------- device scratch ----------------
__device__ __align__(1024) __nv_bfloat16 g_CWc[(size_t)NA * NH * K3CA];  // comm per target agent i: [o][k]
__device__ __align__(1024) __nv_bfloat16 g_CWb2[(size_t)NA * NH * K3L]; // cell per agent: [o][k]
__device__ __align__(1024) __nv_bfloat16 g_xs[(size_t)TSTEPS * B_ * 256];// x split: [t][b][hi|lo]
__device__ __align__(1024) __nv_bfloat16 g_hA[(size_t)B_ * K3C];        // h split A': [b][hi|lo|hi]
__device__ __align__(1024) float g_h[(size_t)B_ * AH];                  // f32 h
__device__ __align__(1024) float g_pre[(size_t)B_ * AH];                // raw cell GEMM out
__device__ __align__(1024) float g_bias[AH];
__device__ int   g_mask_mode;

// ---------------- helpers ----------------
__device__ __forceinline__ uint32_t smem_u32(const void* p) {
    uint32_t a;
    asm("{ .reg .u64 t; cvta.to.shared.u64 t, %1; cvt.u32.u64 %0, t; }" : "=r"(a) : "l"(p));
    return a;
}
#define SWZ(x) ((x) ^ (((x) >> 3) & 0x70))

__device__ __forceinline__ void cp16(uint32_t dst, const void* src) {
    asm volatile("cp.async.cg.shared.global [%0], [%1], 16;" :: "r"(dst), "l"(src));
}
#define CP_COMMIT() asm volatile("cp.async.commit_group;" ::: "memory")
#define CP_WAIT2()  asm volatile("cp.async.wait_group 2;" ::: "memory")
#define CP_WAIT0()  asm volatile("cp.async.wait_group 0;" ::: "memory")

__device__ __forceinline__ void ldm_x4(uint32_t addr, uint32_t& r0, uint32_t& r1,
                                       uint32_t& r2, uint32_t& r3) {
    asm volatile("ldmatrix.sync.aligned.m8n8.x4.shared.b16 {%0,%1,%2,%3}, [%4];"
                 : "=r"(r0), "=r"(r1), "=r"(r2), "=r"(r3) : "r"(addr));
}
__device__ __forceinline__ void mma16816(float* c, const uint32_t* a, uint32_t b0, uint32_t b1) {
    asm volatile("mma.sync.aligned.m16n8k16.row.col.f32.bf16.bf16.f32 "
                 "{%0,%1,%2,%3}, {%4,%5,%6,%7}, {%8,%9}, {%0,%1,%2,%3};"
                 : "+f"(c[0]), "+f"(c[1]), "+f"(c[2]), "+f"(c[3])
                 : "r"(a[0]), "r"(a[1]), "r"(a[2]), "r"(a[3]), "r"(b0), "r"(b1));
}

// ---------------- mask dtype detection ----------------
__global__ void detect_mask_kernel(const unsigned char* __restrict__ m) {
    __shared__ int c1, c2;
    if (threadIdx.x == 0) { c1 = 0; c2 = 0; }
    __syncthreads();
    int l1 = 0, l2 = 0;
    for (int i = threadIdx.x; i < 16384; i += blockDim.x) {
        if (m[4 * i + 1]) l1++;
        if (m[4 * i + 2] | m[4 * i + 3]) l2++;
    }
    atomicAdd(&c1, l1);
    atomicAdd(&c2, l2);
    __syncthreads();
    if (threadIdx.x == 0) g_mask_mode = (c1 > 0) ? 0 : ((c2 > 0) ? 1 : 2);
}

// ---------------- prep ----------------
__global__ void prep_kernel(const float* __restrict__ x,
                            const float* __restrict__ Wc, const void* __restrict__ maskv,
                            const float* __restrict__ Whh, const float* __restrict__ Win,
                            const float* __restrict__ bin, const float* __restrict__ bhh) {
    const int mode = g_mask_mode;
    const unsigned char* m8 = (const unsigned char*)maskv;
    const float*         mf = (const float*)maskv;
    const int*           mi = (const int*)maskv;
    const size_t stride = (size_t)blockDim.x * gridDim.x;
    const size_t t0 = (size_t)blockIdx.x * blockDim.x + threadIdx.x;

    // comm weights per target agent i: B[i][o][k], k = s*1536 + jj*512 + h, j = jj + (jj>=i)
    // s=0,1 -> hi ; s=2 -> lo   (pairs with A sections hi@0 / lo@2048 / hi@4096)
    for (size_t idx = t0; idx < (size_t)NA * NH * K3CA; idx += stride) {
        int k = (int)(idx % K3CA);
        int r = (int)(idx / K3CA);
        int o = r & (NH - 1);
        int i = r >> 9;
        int s = k / 1536, rr = k % 1536;
        int jj = rr >> 9, h = rr & (NH - 1);
        int j = jj + (jj >= i);
        size_t widx = (((size_t)j * NA + i) * NH + h) * NH + o;
        bool msk = (mode == 0) ? (m8[widx] != 0)
                 : (mode == 1) ? (mf[widx] != 0.0f)
                               : (mi[widx] != 0);
        float w = msk ? Wc[widx] * 0.1f : 0.0f;
        __nv_bfloat16 hi = __float2bfloat16(w);
        if (s < 2) g_CWc[idx] = hi;
        else       g_CWc[idx] = __float2bfloat16(w - __bfloat162float(hi));
    }
    // cell weights Whh part: hi at k, hi at 640+k, lo at 1280+k
    for (size_t idx = t0; idx < (size_t)NA * NH * NH; idx += stride) {
        int k = (int)(idx & (NH - 1));
        int r = (int)(idx >> 9);
        int o = r & (NH - 1);
        int a = r >> 9;
        float w = Whh[idx];
        __nv_bfloat16 hi = __float2bfloat16(w);
        __nv_bfloat16 lo = __float2bfloat16(w - __bfloat162float(hi));
        __nv_bfloat16* row = g_CWb2 + ((size_t)a * NH + o) * K3L;
        row[k] = hi; row[640 + k] = hi; row[1280 + k] = lo;
    }
    // cell weights Win part: hi at 512+k, hi at 1152+k, lo at 1792+k
    for (size_t idx = t0; idx < (size_t)NA * NH * NIN; idx += stride) {
        int k = (int)(idx & (NIN - 1));
        int r = (int)(idx >> 7);
        int o = r & (NH - 1);
        int a = r >> 9;
        float w = Win[idx];
        __nv_bfloat16 hi = __float2bfloat16(w);
        __nv_bfloat16 lo = __float2bfloat16(w - __bfloat162float(hi));
        __nv_bfloat16* row = g_CWb2 + ((size_t)a * NH + o) * K3L;
        row[512 + k] = hi; row[1152 + k] = hi; row[1792 + k] = lo;
    }
    // x split
    for (size_t idx = t0; idx < (size_t)TSTEPS * B_ * NIN; idx += stride) {
        int k = (int)(idx & (NIN - 1));
        size_t tb = idx >> 7;
        float v = x[idx];
        __nv_bfloat16 hi = __float2bfloat16(v);
        __nv_bfloat16 lo = __float2bfloat16(v - __bfloat162float(hi));
        __nv_bfloat16* row = g_xs + tb * 256;
        row[k] = hi; row[128 + k] = lo;
    }
    for (size_t idx = t0; idx < (size_t)AH; idx += stride)
        g_bias[idx] = bin[idx] + bhh[idx];
    for (size_t idx = t0; idx < (size_t)B_ * AH; idx += stride)
        g_h[idx] = 0.0f;
    uint32_t* hA32 = (uint32_t*)g_hA;
    for (size_t idx = t0; idx < (size_t)B_ * K3C / 2; idx += stride)
        hA32[idx] = 0u;
}

// ---------------- HMMA machinery: BM=64, BN=128, BK=64, 8 warps (warp tile 32x32) ----------------
#define STAGE 24576            // A 8KB + B 16KB
#define SMEM_DYN (4 * STAGE + 1024)

__device__ __forceinline__ void load_chunk(uint32_t tiles, int s, int tid,
                                           const __nv_bfloat16* aSeg, int aStride,
                                           const __nv_bfloat16* bRow0, int bStride,
                                           int mBase, int nBase, int k0b) {
    uint32_t aAddr = tiles + s * STAGE;
    uint32_t bAddr = aAddr + 8192;
#pragma unroll
    for (int u = 0; u < 2; u++) {
        int i = tid * 2 + u;
        int r = i >> 3, g = i & 7;
        cp16(aAddr + SWZ(r * 128 + g * 16), aSeg + (size_t)(mBase + r) * aStride + g * 8);
    }
#pragma unroll
    for (int u = 0; u < 4; u++) {
        int i = tid * 4 + u;
        int r = i >> 3, g = i & 7;
        cp16(bAddr + SWZ(r * 128 + g * 16), bRow0 + (size_t)(nBase + r) * bStride + k0b + g * 8);
    }
    CP_COMMIT();
}

__device__ __forceinline__ void compute_chunk(uint32_t aBase, uint32_t bBase,
                                              int wm, int wn, int lane,
                                              float acc[2][4][4]) {
#pragma unroll
    for (int ks = 0; ks < 4; ks++) {
        const int kb = ks * 32 + (lane >> 4) * 16;
        uint32_t af[2][4];
#pragma unroll
        for (int mt = 0; mt < 2; mt++) {
            int row = wm + mt * 16 + (lane & 15);
            ldm_x4(aBase + SWZ(row * 128 + kb), af[mt][0], af[mt][1], af[mt][2], af[mt][3]);
        }
        uint32_t bf[4][2];
#pragma unroll
        for (int ng = 0; ng < 2; ng++) {
            int row = wn + ng * 16 + (lane & 15);
            uint32_t r0, r1, r2, r3;
            ldm_x4(bBase + SWZ(row * 128 + kb), r0, r1, r2, r3);
            bf[ng * 2][0] = r0; bf[ng * 2 + 1][0] = r1;
            bf[ng * 2][1] = r2; bf[ng * 2 + 1][1] = r3;
        }
#pragma unroll
        for (int mt = 0; mt < 2; mt++)
#pragma unroll
            for (int nt = 0; nt < 4; nt++)
                mma16816(acc[mt][nt], af[mt], bf[nt][0], bf[nt][1]);
    }
}

// ---------------- fused per-step GEMM: comm blocks [0,commBlocks) + cell blocks ----------------
// comm (agent i): conn[i](512x512) = A'(512 x 4608) @ g_CWc[i](512 x 4608)^T
// cell (agent a): pre [a](512x512) = A'(512 x 1920) @ g_CWb2[a](512 x 1920)^T
__global__ __launch_bounds__(256) void step_gemm(int t, float* __restrict__ conn, int commBlocks) {
    extern __shared__ char dsm[];
    uint32_t tiles = (smem_u32(dsm) + 1023) & ~1023u;
    const int tid = threadIdx.x, wid = tid >> 5, lane = tid & 31;
    const int wm = (wid & 1) * 32, wn = (wid >> 1) * 32;

    float acc[2][4][4];
#pragma unroll
    for (int i = 0; i < 2; i++)
#pragma unroll
        for (int j = 0; j < 4; j++)
#pragma unroll
            for (int q = 0; q < 4; q++) acc[i][j][q] = 0.0f;

    if ((int)blockIdx.x < commBlocks) {
        // ---------------- comm part ----------------
        const int cid = blockIdx.x;
        const int ag = cid >> 5;
        const int rest = cid & 31;
        const int nBase = (rest & 3) * 128;      // over NH (o)
        const int mBase = (rest >> 2) * 64;      // over B_
        const __nv_bfloat16* Brow = g_CWc + (size_t)ag * NH * K3CA;

        auto aoff = [&](int c) -> int {          // A column offset for chunk c
            int s = c / 24, rr = c % 24;
            int jj = rr >> 3, r8 = rr & 7;
            int j = jj + (jj >= ag);
            return s * 2048 + j * 512 + r8 * 64;
        };

        const int C = K3CA / 64;                 // 72
        for (int p = 0; p < 3; p++)
            load_chunk(tiles, p, tid, g_hA + aoff(p), K3C, Brow, K3CA, mBase, nBase, p * 64);

        for (int c = 0; c < C; c++) {
            const int s = c & 3;
            if (c + 3 < C) CP_WAIT2(); else CP_WAIT0();
            __syncthreads();
            compute_chunk(tiles + s * STAGE, tiles + s * STAGE + 8192, wm, wn, lane, acc);
            const int n = c + 3;
            if (n < C)
                load_chunk(tiles, n & 3, tid, g_hA + aoff(n), K3C, Brow, K3CA, mBase, nBase, n * 64);
        }
        // epilogue: conn[ag, b, o]
#pragma unroll
        for (int mt = 0; mt < 2; mt++) {
#pragma unroll
            for (int nt = 0; nt < 4; nt++) {
                const int r = mBase + wm + mt * 16 + (lane >> 2);
                const int col = nBase + wn + nt * 8 + (lane & 3) * 2;
                *(float2*)(conn + ((size_t)ag * B_ + r) * NH + col) =
                    make_float2(acc[mt][nt][0], acc[mt][nt][1]);
                *(float2*)(conn + ((size_t)ag * B_ + r + 8) * NH + col) =
                    make_float2(acc[mt][nt][2], acc[mt][nt][3]);
            }
        }
    } else {
        // ---------------- cell part ----------------
        const int cid = blockIdx.x - commBlocks;
        const int a = cid >> 5;
        const int rest = cid & 31;
        const int nBase = (rest & 3) * 128;      // over NH (o)
        const int mBase = (rest >> 2) * 64;      // over B_
        const __nv_bfloat16* Brow = g_CWb2 + (size_t)a * NH * K3L;
        const __nv_bfloat16* xsT = g_xs + (size_t)t * B_ * 256;

        auto aseg = [&](int c, const __nv_bfloat16*& seg, int& rs) {
            if (c < 8)       { seg = g_hA + a * NH + c * 64;               rs = K3C; }
            else if (c < 10) { seg = xsT + (c - 8) * 64;                   rs = 256; }
            else if (c < 18) { seg = g_hA + 2048 + a * NH + (c - 10) * 64; rs = K3C; }
            else if (c < 20) { seg = xsT + 128 + (c - 18) * 64;            rs = 256; }
            else if (c < 28) { seg = g_hA + a * NH + (c - 20) * 64;        rs = K3C; }
            else             { seg = xsT + (c - 28) * 64;                  rs = 256; }
        };

        const int C = K3L / 64;                  // 30
        for (int p = 0; p < 3; p++) {
            const __nv_bfloat16* seg; int rs; aseg(p, seg, rs);
            load_chunk(tiles, p, tid, seg, rs, Brow, K3L, mBase, nBase, p * 64);
        }
        for (int c = 0; c < C; c++) {
            const int s = c & 3;
            if (c + 3 < C) CP_WAIT2(); else CP_WAIT0();
            __syncthreads();
            compute_chunk(tiles + s * STAGE, tiles + s * STAGE + 8192, wm, wn, lane, acc);
            const int n = c + 3;
            if (n < C) {
                const __nv_bfloat16* seg; int rs; aseg(n, seg, rs);
                load_chunk(tiles, n & 3, tid, seg, rs, Brow, K3L, mBase, nBase, n * 64);
            }
        }
        // epilogue: raw pre[b][a*NH+o]
#pragma unroll
        for (int mt = 0; mt < 2; mt++) {
#pragma unroll
            for (int nt = 0; nt < 4; nt++) {
                const int r = mBase + wm + mt * 16 + (lane >> 2);
                const int o = nBase + wn + nt * 8 + (lane & 3) * 2;
                *(float2*)(g_pre + (size_t)r * AH + a * NH + o) =
                    make_float2(acc[mt][nt][0], acc[mt][nt][1]);
                *(float2*)(g_pre + (size_t)(r + 8) * AH + a * NH + o) =
                    make_float2(acc[mt][nt][2], acc[mt][nt][3]);
            }
        }
    }
}

// ---------------- epilogue: tanh + state update + readout (one block per batch row) ----------------
__global__ __launch_bounds__(256) void step_epilogue(const float* __restrict__ conn, int hasComm,
                                                     const float* __restrict__ Wro,
                                                     const float* __restrict__ bro,
                                                     float* __restrict__ out_y) {
    __shared__ float sh[AH];
    __shared__ float sred[8][NOUT];
    const int b = blockIdx.x;
    const int tid = threadIdx.x;

    for (int idx = tid; idx < AH; idx += 256) {
        const int a = idx >> 9, o = idx & (NH - 1);
        float v = g_pre[(size_t)b * AH + idx] + g_bias[idx];
        if (hasComm) v += conn[((size_t)a * B_ + b) * NH + o];
        v = tanhf(v);
        sh[idx] = v;
        g_h[(size_t)b * AH + idx] = v;
        __nv_bfloat16 hi = __float2bfloat16(v);
        __nv_bfloat16 lo = __float2bfloat16(v - __bfloat162float(hi));
        __nv_bfloat16* hp = g_hA + (size_t)b * K3C;
        hp[idx] = hi; hp[2048 + idx] = lo; hp[4096 + idx] = hi;
    }
    __syncthreads();

    float acc[NOUT];
#pragma unroll
    for (int n = 0; n < NOUT; n++) acc[n] = 0.0f;
#pragma unroll
    for (int q = 0; q < 2; q++) {
        const int k = (q * 256 + tid) * 4;
        const float4 h4 = *(const float4*)(sh + k);
#pragma unroll
        for (int n = 0; n < NOUT; n++) {
            const float4 w4 = __ldg((const float4*)(Wro + (size_t)n * AH + k));
            acc[n] += h4.x * w4.x + h4.y * w4.y + h4.z * w4.z + h4.w * w4.w;
        }
    }
    const int warp = tid >> 5, lane = tid & 31;
#pragma unroll
    for (int n = 0; n < NOUT; n++) {
#pragma unroll
        for (int off = 16; off > 0; off >>= 1)
            acc[n] += __shfl_xor_sync(0xFFFFFFFFu, acc[n], off);
        if (lane == 0) sred[warp][n] = acc[n];
    }
    __syncthreads();
    if (tid < NOUT) {
        float s = 0.0f;
#pragma unroll
        for (int w = 0; w < 8; w++) s += sred[w][tid];
        out_y[(size_t)b * NOUT + tid] = s + bro[tid];
    }
}

// ---------------- h_final ----------------
__global__ void final_copy_kernel(float* __restrict__ hf) {
    const size_t stride = (size_t)blockDim.x * gridDim.x;
    for (size_t idx = (size_t)blockIdx.x * blockDim.x + threadIdx.x;
         idx < (size_t)NA * B_ * NH; idx += stride) {
        int o = (int)(idx & (NH - 1));
        int b = (int)((idx >> 9) & (B_ - 1));
        int a = (int)(idx >> 18);
        hf[idx] = g_h[(size_t)b * AH + a * NH + o];
    }
}

// ---------------- launch ----------------
extern "C" void kernel_launch(void* const* d_in, const int* in_sizes, int n_in,
                              void* d_out, int out_size) {
    const float* x   = (const float*)d_in[0];
    const float* Win = (const float*)d_in[1];
    const float* bin = (const float*)d_in[2];
    const float* Whh = (const float*)d_in[3];
    const float* bhh = (const float*)d_in[4];
    const float* Wc  = (const float*)d_in[5];
    const float* Wro = (const float*)d_in[6];
    const float* bro = (const float*)d_in[7];
    const void*  msk = d_in[8];

    float* out       = (float*)d_out;
    float* out_y     = out;
    float* out_hf    = out + (size_t)TSTEPS * B_ * NOUT;
    float* out_conn  = out_hf + (size_t)NA * B_ * NH;

    cudaFuncSetAttribute(step_gemm, cudaFuncAttributeMaxDynamicSharedMemorySize, SMEM_DYN);

    detect_mask_kernel<<<1, 256>>>((const unsigned char*)msk);
    prep_kernel<<<2048, 256>>>(x, Wc, msk, Whh, Win, bin, bhh);

    for (int t = 0; t < TSTEPS; t++) {
        float* connT = out_conn + (size_t)(t - 1) * NA * B_ * NH;
        if (t >= 1) step_gemm<<<256, 256, SMEM_DYN>>>(t, connT, 128);
        else        step_gemm<<<128, 256, SMEM_DYN>>>(t, nullptr, 0);
        step_epilogue<<<B_, 256>>>((t >= 1) ? connT : nullptr, (t >= 1) ? 1 : 0,
                                   Wro, bro, out_y + (size_t)t * B_ * NOUT);
    }
    final_copy_kernel<<<512, 256>>>(out_hf);
}

// round 7
// speedup vs baseline: 4.1032x; 1.3879x over previous
#include <cuda_runtime.h>
#include <cuda_fp16.h>
#include <cstdint>
#include <cstddef>

#define TSTEPS 64
#define B_     512
#define NA     4
#define NIN    128
#define NH     512
#define NOUT   10
#define AH     2048      // NA * NH
#define KHA    4096      // h split-2 width: [hi(2048)|lo(2048)]
#define KCW    1536      // comm weight width per agent (j != i), reused for both A sections
#define KLW    640       // cell weight width: [Whh 512 | Win 128], reused for both A sections

// ---------------- device scratch ----------------
__device__ __align__(1024) __half g_CWc[(size_t)NA * NH * KCW];    // comm W_hi per target agent
__device__ __align__(1024) __half g_CWl[(size_t)NA * NH * KLW];    // cell W_hi per agent
__device__ __align__(1024) __half g_xs[(size_t)TSTEPS * B_ * 256]; // x split: [t][b][hi128|lo128]
__device__ __align__(1024) __half g_hA[(size_t)B_ * KHA];          // h split: [b][hi|lo]
__device__ __align__(1024) float g_hist[(size_t)TSTEPS * B_ * AH]; // h history (f32)
__device__ __align__(1024) float g_bias[AH];
__device__ int g_flags[TSTEPS];
__device__ int g_mask_mode;

// ---------------- helpers ----------------
__device__ __forceinline__ uint32_t smem_u32(const void* p) {
    uint32_t a;
    asm("{ .reg .u64 t; cvta.to.shared.u64 t, %1; cvt.u32.u64 %0, t; }" : "=r"(a) : "l"(p));
    return a;
}
#define SWZ(x) ((x) ^ (((x) >> 3) & 0x70))

__device__ __forceinline__ void cp16(uint32_t dst, const void* src) {
    asm volatile("cp.async.cg.shared.global [%0], [%1], 16;" :: "r"(dst), "l"(src));
}
#define CP_COMMIT() asm volatile("cp.async.commit_group;" ::: "memory")
#define CP_WAIT2()  asm volatile("cp.async.wait_group 2;" ::: "memory")
#define CP_WAIT0()  asm volatile("cp.async.wait_group 0;" ::: "memory")

__device__ __forceinline__ void ldm_x4(uint32_t addr, uint32_t& r0, uint32_t& r1,
                                       uint32_t& r2, uint32_t& r3) {
    asm volatile("ldmatrix.sync.aligned.m8n8.x4.shared.b16 {%0,%1,%2,%3}, [%4];"
                 : "=r"(r0), "=r"(r1), "=r"(r2), "=r"(r3) : "r"(addr));
}
__device__ __forceinline__ void mma16816h(float* c, const uint32_t* a, uint32_t b0, uint32_t b1) {
    asm volatile("mma.sync.aligned.m16n8k16.row.col.f32.f16.f16.f32 "
                 "{%0,%1,%2,%3}, {%4,%5,%6,%7}, {%8,%9}, {%0,%1,%2,%3};"
                 : "+f"(c[0]), "+f"(c[1]), "+f"(c[2]), "+f"(c[3])
                 : "r"(a[0]), "r"(a[1]), "r"(a[2]), "r"(a[3]), "r"(b0), "r"(b1));
}

// ---------------- mask dtype detection ----------------
__global__ void detect_mask_kernel(const unsigned char* __restrict__ m) {
    __shared__ int c1, c2;
    if (threadIdx.x == 0) { c1 = 0; c2 = 0; }
    __syncthreads();
    int l1 = 0, l2 = 0;
    for (int i = threadIdx.x; i < 16384; i += blockDim.x) {
        if (m[4 * i + 1]) l1++;
        if (m[4 * i + 2] | m[4 * i + 3]) l2++;
    }
    atomicAdd(&c1, l1);
    atomicAdd(&c2, l2);
    __syncthreads();
    if (threadIdx.x == 0) g_mask_mode = (c1 > 0) ? 0 : ((c2 > 0) ? 1 : 2);
}

// ---------------- prep ----------------
__global__ void prep_kernel(const float* __restrict__ x,
                            const float* __restrict__ Wc, const void* __restrict__ maskv,
                            const float* __restrict__ Whh, const float* __restrict__ Win,
                            const float* __restrict__ bin, const float* __restrict__ bhh) {
    const int mode = g_mask_mode;
    const unsigned char* m8 = (const unsigned char*)maskv;
    const float*         mf = (const float*)maskv;
    const int*           mi = (const int*)maskv;
    const size_t stride = (size_t)blockDim.x * gridDim.x;
    const size_t t0 = (size_t)blockIdx.x * blockDim.x + threadIdx.x;

    // comm weights: g_CWc[i][o][k], k = jj*512 + h, j = jj + (jj>=i); fp16(w*0.1)
    for (size_t idx = t0; idx < (size_t)NA * NH * KCW; idx += stride) {
        int k = (int)(idx % KCW);
        int r = (int)(idx / KCW);
        int o = r & (NH - 1);
        int i = r >> 9;
        int jj = k >> 9, h = k & (NH - 1);
        int j = jj + (jj >= i);
        size_t widx = (((size_t)j * NA + i) * NH + h) * NH + o;
        bool msk = (mode == 0) ? (m8[widx] != 0)
                 : (mode == 1) ? (mf[widx] != 0.0f)
                               : (mi[widx] != 0);
        g_CWc[idx] = __float2half(msk ? Wc[widx] * 0.1f : 0.0f);
    }
    // cell weights: g_CWl[a][o][k]: k<512 -> Whh[a][o][k]; else Win[a][o][k-512]
    for (size_t idx = t0; idx < (size_t)NA * NH * KLW; idx += stride) {
        int k = (int)(idx % KLW);
        int r = (int)(idx / KLW);
        int o = r & (NH - 1);
        int a = r >> 9;
        float w = (k < NH) ? Whh[((size_t)a * NH + o) * NH + k]
                           : Win[((size_t)a * NH + o) * NIN + (k - NH)];
        g_CWl[idx] = __float2half(w);
    }
    // x split-2 fp16
    for (size_t idx = t0; idx < (size_t)TSTEPS * B_ * NIN; idx += stride) {
        int k = (int)(idx & (NIN - 1));
        size_t tb = idx >> 7;
        float v = x[idx];
        __half hi = __float2half(v);
        __half lo = __float2half(v - __half2float(hi));
        __half* row = g_xs + tb * 256;
        row[k] = hi; row[128 + k] = lo;
    }
    for (size_t idx = t0; idx < (size_t)AH; idx += stride)
        g_bias[idx] = bin[idx] + bhh[idx];
    uint32_t* hA32 = (uint32_t*)g_hA;
    for (size_t idx = t0; idx < (size_t)B_ * KHA / 2; idx += stride)
        hA32[idx] = 0u;
    for (size_t idx = t0; idx < TSTEPS; idx += stride)
        g_flags[idx] = 0;
}

// ---------------- HMMA machinery: BM=64, BN=128, BK=64, 8 warps ----------------
#define STAGE 24576            // A 8KB + B 16KB
#define SMEM_DYN (4 * STAGE + 1024)

__device__ __forceinline__ void load_chunk(uint32_t tiles, int s, int tid,
                                           const __half* aSeg, int aStride,
                                           const __half* bRow0, int bStride,
                                           int mBase, int nBase, int k0b) {
    uint32_t aAddr = tiles + s * STAGE;
    uint32_t bAddr = aAddr + 8192;
#pragma unroll
    for (int u = 0; u < 2; u++) {
        int i = tid * 2 + u;
        int r = i >> 3, g = i & 7;
        cp16(aAddr + SWZ(r * 128 + g * 16), aSeg + (size_t)(mBase + r) * aStride + g * 8);
    }
#pragma unroll
    for (int u = 0; u < 4; u++) {
        int i = tid * 4 + u;
        int r = i >> 3, g = i & 7;
        cp16(bAddr + SWZ(r * 128 + g * 16), bRow0 + (size_t)(nBase + r) * bStride + k0b + g * 8);
    }
    CP_COMMIT();
}

__device__ __forceinline__ void compute_chunk(uint32_t aBase, uint32_t bBase,
                                              int wm, int wn, int lane,
                                              float acc[2][4][4]) {
#pragma unroll
    for (int ks = 0; ks < 4; ks++) {
        const int kb = ks * 32 + (lane >> 4) * 16;
        uint32_t af[2][4];
#pragma unroll
        for (int mt = 0; mt < 2; mt++) {
            int row = wm + mt * 16 + (lane & 15);
            ldm_x4(aBase + SWZ(row * 128 + kb), af[mt][0], af[mt][1], af[mt][2], af[mt][3]);
        }
        uint32_t bf[4][2];
#pragma unroll
        for (int ng = 0; ng < 2; ng++) {
            int row = wn + ng * 16 + (lane & 15);
            uint32_t r0, r1, r2, r3;
            ldm_x4(bBase + SWZ(row * 128 + kb), r0, r1, r2, r3);
            bf[ng * 2][0] = r0; bf[ng * 2 + 1][0] = r1;
            bf[ng * 2][1] = r2; bf[ng * 2 + 1][1] = r3;
        }
#pragma unroll
        for (int mt = 0; mt < 2; mt++)
#pragma unroll
            for (int nt = 0; nt < 4; nt++)
                mma16816h(acc[mt][nt], af[mt], bf[nt][0], bf[nt][1]);
    }
}

// ---------------- fused step kernel ----------------
// comm CTA (agent i): conn[i](512x512) = hA(512 x 3072 eff) @ W_hi^T ; then flag release
// cell CTA (agent a): acc = [h|x] split-2 GEMM (K=1280); wait flag; epilogue tanh -> hist + hA
__global__ __launch_bounds__(256, 2) void step_gemm(int t, float* __restrict__ conn,
                                                    int commCount) {
    extern __shared__ char dsm[];
    uint32_t tiles = (smem_u32(dsm) + 1023) & ~1023u;
    const int tid = threadIdx.x, wid = tid >> 5, lane = tid & 31;
    const int wm = (wid & 1) * 32, wn = (wid >> 1) * 32;

    // role assignment: pair comm+cell on each SM (classic launch maps bid%148 -> SM)
    int isComm, cidx;
    if (commCount) {
        if ((int)blockIdx.x < 148) { isComm = !(blockIdx.x & 1); cidx = blockIdx.x >> 1; }
        else { int r = blockIdx.x - 148; isComm = (r & 1); cidx = 74 + (r >> 1); }
    } else { isComm = 0; cidx = blockIdx.x; }

    const int ag = cidx >> 5;
    const int rest = cidx & 31;
    const int nBase = (rest & 3) * 128;      // over NH (o)
    const int mBase = (rest >> 2) * 64;      // over B_

    float acc[2][4][4];
#pragma unroll
    for (int i = 0; i < 2; i++)
#pragma unroll
        for (int j = 0; j < 4; j++)
#pragma unroll
            for (int q = 0; q < 4; q++) acc[i][j][q] = 0.0f;

    if (isComm) {
        const __half* Brow = g_CWc + (size_t)ag * NH * KCW;
        auto aoff = [&](int c) -> int {      // A col offset for chunk c (C=48)
            int s = c / 24, rr = c % 24;
            int jj = rr >> 3, r8 = rr & 7;
            int j = jj + (jj >= ag);
            return s * 2048 + j * 512 + r8 * 64;
        };
        const int C = 48;
        for (int p = 0; p < 3; p++)
            load_chunk(tiles, p, tid, g_hA + aoff(p), KHA, Brow, KCW, mBase, nBase, (p % 24) * 64);
        for (int c = 0; c < C; c++) {
            const int s = c & 3;
            if (c + 3 < C) CP_WAIT2(); else CP_WAIT0();
            __syncthreads();
            compute_chunk(tiles + s * STAGE, tiles + s * STAGE + 8192, wm, wn, lane, acc);
            const int n = c + 3;
            if (n < C)
                load_chunk(tiles, n & 3, tid, g_hA + aoff(n), KHA, Brow, KCW, mBase, nBase, (n % 24) * 64);
        }
        // write conn tile, then release
#pragma unroll
        for (int mt = 0; mt < 2; mt++) {
#pragma unroll
            for (int nt = 0; nt < 4; nt++) {
                const int r = mBase + wm + mt * 16 + (lane >> 2);
                const int col = nBase + wn + nt * 8 + (lane & 3) * 2;
                *(float2*)(conn + ((size_t)ag * B_ + r) * NH + col) =
                    make_float2(acc[mt][nt][0], acc[mt][nt][1]);
                *(float2*)(conn + ((size_t)ag * B_ + r + 8) * NH + col) =
                    make_float2(acc[mt][nt][2], acc[mt][nt][3]);
            }
        }
        __syncthreads();
        __threadfence();
        if (tid == 0) atomicAdd(&g_flags[t], 1);
    } else {
        const __half* Brow = g_CWl + (size_t)ag * NH * KLW;
        const __half* xsT = g_xs + (size_t)t * B_ * 256;
        auto aseg = [&](int c, const __half*& seg, int& rs, int& k0b) {  // C=20
            int s = c / 10, rr = c % 10;
            if (rr < 8) { seg = g_hA + s * 2048 + ag * 512 + rr * 64; rs = KHA; k0b = rr * 64; }
            else        { seg = xsT + s * 128 + (rr - 8) * 64;        rs = 256; k0b = 512 + (rr - 8) * 64; }
        };
        const int C = 20;
        for (int p = 0; p < 3; p++) {
            const __half* seg; int rs, k0b; aseg(p, seg, rs, k0b);
            load_chunk(tiles, p, tid, seg, rs, Brow, KLW, mBase, nBase, k0b);
        }
        for (int c = 0; c < C; c++) {
            const int s = c & 3;
            if (c + 3 < C) CP_WAIT2(); else CP_WAIT0();
            __syncthreads();
            compute_chunk(tiles + s * STAGE, tiles + s * STAGE + 8192, wm, wn, lane, acc);
            const int n = c + 3;
            if (n < C) {
                const __half* seg; int rs, k0b; aseg(n, seg, rs, k0b);
                load_chunk(tiles, n & 3, tid, seg, rs, Brow, KLW, mBase, nBase, k0b);
            }
        }
        // wait for comm CTAs (all co-resident: 2 CTAs/SM guaranteed by launch bounds)
        if (commCount) {
            if (tid == 0) {
                while (atomicAdd(&g_flags[t], 0) < commCount) __nanosleep(64);
            }
            __syncthreads();
            __threadfence();
        }
        // epilogue: bias + conn + tanh -> hist f32 + hA fp16 split
        float* hist = g_hist + (size_t)t * B_ * AH;
#pragma unroll
        for (int mt = 0; mt < 2; mt++) {
#pragma unroll
            for (int nt = 0; nt < 4; nt++) {
                const int r0 = mBase + wm + mt * 16 + (lane >> 2);
                const int o = nBase + wn + nt * 8 + (lane & 3) * 2;
                const float2 bias2 = *(const float2*)(g_bias + ag * NH + o);
#pragma unroll
                for (int h2 = 0; h2 < 2; h2++) {
                    const int b = r0 + h2 * 8;
                    float v0 = acc[mt][nt][h2 * 2 + 0] + bias2.x;
                    float v1 = acc[mt][nt][h2 * 2 + 1] + bias2.y;
                    if (commCount) {
                        const float2 cm = *(const float2*)(conn + ((size_t)ag * B_ + b) * NH + o);
                        v0 += cm.x; v1 += cm.y;
                    }
                    v0 = tanhf(v0); v1 = tanhf(v1);
                    *(float2*)(hist + (size_t)b * AH + ag * NH + o) = make_float2(v0, v1);
                    __half h0 = __float2half(v0), h1 = __float2half(v1);
                    __half l0 = __float2half(v0 - __half2float(h0));
                    __half l1 = __float2half(v1 - __half2float(h1));
                    __half* hp = g_hA + (size_t)b * KHA + ag * NH + o;
                    hp[0] = h0; hp[1] = h1;
                    hp[2048] = l0; hp[2049] = l1;
                }
            }
        }
    }
}

// ---------------- readout over all timesteps ----------------
__global__ __launch_bounds__(256) void readout_all(const float* __restrict__ Wro,
                                                   const float* __restrict__ bro,
                                                   float* __restrict__ out_y) {
    __shared__ float sred[8][NOUT];
    const int b = blockIdx.x, t = blockIdx.y;
    const int tid = threadIdx.x;
    const float* hrow = g_hist + ((size_t)t * B_ + b) * AH;
    float acc[NOUT];
#pragma unroll
    for (int n = 0; n < NOUT; n++) acc[n] = 0.0f;
#pragma unroll
    for (int q = 0; q < 2; q++) {
        const int k = (q * 256 + tid) * 4;
        const float4 h4 = *(const float4*)(hrow + k);
#pragma unroll
        for (int n = 0; n < NOUT; n++) {
            const float4 w4 = __ldg((const float4*)(Wro + (size_t)n * AH + k));
            acc[n] += h4.x * w4.x + h4.y * w4.y + h4.z * w4.z + h4.w * w4.w;
        }
    }
    const int warp = tid >> 5, lane = tid & 31;
#pragma unroll
    for (int n = 0; n < NOUT; n++) {
#pragma unroll
        for (int off = 16; off > 0; off >>= 1)
            acc[n] += __shfl_xor_sync(0xFFFFFFFFu, acc[n], off);
        if (lane == 0) sred[warp][n] = acc[n];
    }
    __syncthreads();
    if (tid < NOUT) {
        float s = 0.0f;
#pragma unroll
        for (int w = 0; w < 8; w++) s += sred[w][tid];
        out_y[((size_t)t * B_ + b) * NOUT + tid] = s + bro[tid];
    }
}

// ---------------- h_final ----------------
__global__ void final_copy_kernel(float* __restrict__ hf) {
    const float* hlast = g_hist + (size_t)(TSTEPS - 1) * B_ * AH;
    const size_t stride = (size_t)blockDim.x * gridDim.x;
    for (size_t idx = (size_t)blockIdx.x * blockDim.x + threadIdx.x;
         idx < (size_t)NA * B_ * NH; idx += stride) {
        int o = (int)(idx & (NH - 1));
        int b = (int)((idx >> 9) & (B_ - 1));
        int a = (int)(idx >> 18);
        hf[idx] = hlast[(size_t)b * AH + a * NH + o];
    }
}

// ---------------- launch ----------------
extern "C" void kernel_launch(void* const* d_in, const int* in_sizes, int n_in,
                              void* d_out, int out_size) {
    const float* x   = (const float*)d_in[0];
    const float* Win = (const float*)d_in[1];
    const float* bin = (const float*)d_in[2];
    const float* Whh = (const float*)d_in[3];
    const float* bhh = (const float*)d_in[4];
    const float* Wc  = (const float*)d_in[5];
    const float* Wro = (const float*)d_in[6];
    const float* bro = (const float*)d_in[7];
    const void*  msk = d_in[8];

    float* out       = (float*)d_out;
    float* out_y     = out;
    float* out_hf    = out + (size_t)TSTEPS * B_ * NOUT;
    float* out_conn  = out_hf + (size_t)NA * B_ * NH;

    cudaFuncSetAttribute(step_gemm, cudaFuncAttributeMaxDynamicSharedMemorySize, SMEM_DYN);

    detect_mask_kernel<<<1, 256>>>((const unsigned char*)msk);
    prep_kernel<<<2048, 256>>>(x, Wc, msk, Whh, Win, bin, bhh);

    for (int t = 0; t < TSTEPS; t++) {
        float* connT = out_conn + (size_t)(t - 1) * NA * B_ * NH;
        if (t >= 1) step_gemm<<<256, 256, SMEM_DYN>>>(t, connT, 128);
        else        step_gemm<<<128, 256, SMEM_DYN>>>(t, nullptr, 0);
    }
    readout_all<<<dim3(B_, TSTEPS), 256>>>(Wro, bro, out_y);
    final_copy_kernel<<<512, 256>>>(out_hf);
}

// round 10
// speedup vs baseline: 4.3651x; 1.0638x over previous
// R10: identical to R9 (container failed twice = suspected infra flake; R8 ran this
// exact queue/spin design). Delta vs R8 remains only the double-buffered g_hA fix.
#include <cuda_runtime.h>
#include <cuda_fp16.h>
#include <cstdint>
#include <cstddef>

#define TSTEPS 64
#define B_     512
#define NA     4
#define NIN    128
#define NH     512
#define NOUT   10
#define AH     2048      // NA * NH
#define KHA    4096      // h split-2 width: [hi(2048)|lo(2048)]
#define KCW    1536      // comm weight width per agent (j != i)
#define KLW    640       // cell weight width: [Whh 512 | Win 128]

// ---------------- device scratch ----------------
__device__ __align__(1024) __half g_CWc[(size_t)NA * NH * KCW];    // comm W per target agent
__device__ __align__(1024) __half g_CWl[(size_t)NA * NH * KLW];    // cell W per agent
__device__ __align__(1024) __half g_xs[(size_t)TSTEPS * B_ * 256]; // x split: [t][b][hi128|lo128]
__device__ __align__(1024) __half g_hA[2][(size_t)B_ * KHA];       // h split, DOUBLE-BUFFERED
__device__ __align__(1024) float g_hist[(size_t)TSTEPS * B_ * AH]; // h history (f32)
__device__ __align__(1024) float g_connP[2][(size_t)NA * B_ * NH]; // comm split-K partials
__device__ __align__(1024) float g_bias[AH];
__device__ int g_qhead[TSTEPS];
__device__ int g_cflag[TSTEPS][128];
__device__ int g_mask_mode;

// ---------------- helpers ----------------
__device__ __forceinline__ uint32_t smem_u32(const void* p) {
    uint32_t a;
    asm("{ .reg .u64 t; cvta.to.shared.u64 t, %1; cvt.u32.u64 %0, t; }" : "=r"(a) : "l"(p));
    return a;
}
#define SWZ(x) ((x) ^ (((x) >> 3) & 0x70))

__device__ __forceinline__ void cp16(uint32_t dst, const void* src) {
    asm volatile("cp.async.cg.shared.global [%0], [%1], 16;" :: "r"(dst), "l"(src));
}
#define CP_COMMIT() asm volatile("cp.async.commit_group;" ::: "memory")
#define CP_WAIT1()  asm volatile("cp.async.wait_group 1;" ::: "memory")
#define CP_WAIT0()  asm volatile("cp.async.wait_group 0;" ::: "memory")

__device__ __forceinline__ void ldm_x4(uint32_t addr, uint32_t& r0, uint32_t& r1,
                                       uint32_t& r2, uint32_t& r3) {
    asm volatile("ldmatrix.sync.aligned.m8n8.x4.shared.b16 {%0,%1,%2,%3}, [%4];"
                 : "=r"(r0), "=r"(r1), "=r"(r2), "=r"(r3) : "r"(addr));
}
__device__ __forceinline__ void mma16816h(float* c, const uint32_t* a, uint32_t b0, uint32_t b1) {
    asm volatile("mma.sync.aligned.m16n8k16.row.col.f32.f16.f16.f32 "
                 "{%0,%1,%2,%3}, {%4,%5,%6,%7}, {%8,%9}, {%0,%1,%2,%3};"
                 : "+f"(c[0]), "+f"(c[1]), "+f"(c[2]), "+f"(c[3])
                 : "r"(a[0]), "r"(a[1]), "r"(a[2]), "r"(a[3]), "r"(b0), "r"(b1));
}

// ---------------- mask dtype detection ----------------
__global__ void detect_mask_kernel(const unsigned char* __restrict__ m) {
    __shared__ int c1, c2;
    if (threadIdx.x == 0) { c1 = 0; c2 = 0; }
    __syncthreads();
    int l1 = 0, l2 = 0;
    for (int i = threadIdx.x; i < 16384; i += blockDim.x) {
        if (m[4 * i + 1]) l1++;
        if (m[4 * i + 2] | m[4 * i + 3]) l2++;
    }
    atomicAdd(&c1, l1);
    atomicAdd(&c2, l2);
    __syncthreads();
    if (threadIdx.x == 0) g_mask_mode = (c1 > 0) ? 0 : ((c2 > 0) ? 1 : 2);
}

// ---------------- prep ----------------
__global__ void prep_kernel(const float* __restrict__ x,
                            const float* __restrict__ Wc, const void* __restrict__ maskv,
                            const float* __restrict__ Whh, const float* __restrict__ Win,
                            const float* __restrict__ bin, const float* __restrict__ bhh) {
    const int mode = g_mask_mode;
    const unsigned char* m8 = (const unsigned char*)maskv;
    const float*         mf = (const float*)maskv;
    const int*           mi = (const int*)maskv;
    const size_t stride = (size_t)blockDim.x * gridDim.x;
    const size_t t0 = (size_t)blockIdx.x * blockDim.x + threadIdx.x;

    // comm weights: g_CWc[i][o][k], k = jj*512 + h, j = jj + (jj>=i); fp16(w*0.1)
    for (size_t idx = t0; idx < (size_t)NA * NH * KCW; idx += stride) {
        int k = (int)(idx % KCW);
        int r = (int)(idx / KCW);
        int o = r & (NH - 1);
        int i = r >> 9;
        int jj = k >> 9, h = k & (NH - 1);
        int j = jj + (jj >= i);
        size_t widx = (((size_t)j * NA + i) * NH + h) * NH + o;
        bool msk = (mode == 0) ? (m8[widx] != 0)
                 : (mode == 1) ? (mf[widx] != 0.0f)
                               : (mi[widx] != 0);
        g_CWc[idx] = __float2half(msk ? Wc[widx] * 0.1f : 0.0f);
    }
    // cell weights: g_CWl[a][o][k]: k<512 -> Whh[a][o][k]; else Win[a][o][k-512]
    for (size_t idx = t0; idx < (size_t)NA * NH * KLW; idx += stride) {
        int k = (int)(idx % KLW);
        int r = (int)(idx / KLW);
        int o = r & (NH - 1);
        int a = r >> 9;
        float w = (k < NH) ? Whh[((size_t)a * NH + o) * NH + k]
                           : Win[((size_t)a * NH + o) * NIN + (k - NH)];
        g_CWl[idx] = __float2half(w);
    }
    // x split-2 fp16
    for (size_t idx = t0; idx < (size_t)TSTEPS * B_ * NIN; idx += stride) {
        int k = (int)(idx & (NIN - 1));
        size_t tb = idx >> 7;
        float v = x[idx];
        __half hi = __float2half(v);
        __half lo = __float2half(v - __half2float(hi));
        __half* row = g_xs + tb * 256;
        row[k] = hi; row[128 + k] = lo;
    }
    for (size_t idx = t0; idx < (size_t)AH; idx += stride)
        g_bias[idx] = bin[idx] + bhh[idx];
    // zero h buffer 0 (read at t=0); buffer 1 is fully written by t=0 before t=1 reads it
    uint32_t* hA32 = (uint32_t*)g_hA[0];
    for (size_t idx = t0; idx < (size_t)B_ * KHA / 2; idx += stride)
        hA32[idx] = 0u;
    for (size_t idx = t0; idx < TSTEPS; idx += stride)
        g_qhead[idx] = 0;
    for (size_t idx = t0; idx < (size_t)TSTEPS * 128; idx += stride)
        ((int*)g_cflag)[idx] = 0;
}

// ---------------- double-chunk HMMA machinery ----------------
// stage: A_hi 64x64 (8KB) @0, A_lo 64x64 @8192, B 128x64 (16KB) @16384
#define STAGE 32768
#define SMEM_DYN (3 * STAGE + 1024)

__device__ __forceinline__ void load_dc(uint32_t tiles, int s, int tid,
                                        const __half* aHi, int aHiStride,
                                        const __half* aLo, int aLoStride,
                                        const __half* bRow, int bStride,
                                        int mBase, int nBase, int k0b) {
    uint32_t base = tiles + s * STAGE;
#pragma unroll
    for (int u = 0; u < 2; u++) {
        int i = tid * 2 + u;              // 0..511
        int r = i >> 3, g = i & 7;
        cp16(base + SWZ(r * 128 + g * 16), aHi + (size_t)(mBase + r) * aHiStride + g * 8);
    }
#pragma unroll
    for (int u = 0; u < 2; u++) {
        int i = tid * 2 + u;
        int r = i >> 3, g = i & 7;
        cp16(base + 8192 + SWZ(r * 128 + g * 16), aLo + (size_t)(mBase + r) * aLoStride + g * 8);
    }
#pragma unroll
    for (int u = 0; u < 4; u++) {
        int i = tid * 4 + u;              // 0..1023
        int r = i >> 3, g = i & 7;
        cp16(base + 16384 + SWZ(r * 128 + g * 16), bRow + (size_t)(nBase + r) * bStride + k0b + g * 8);
    }
    CP_COMMIT();
}

__device__ __forceinline__ void compute_dc(uint32_t st, int wm, int wn, int lane,
                                           float acc[2][4][4]) {
    const uint32_t aHiB = st, aLoB = st + 8192, bB = st + 16384;
#pragma unroll
    for (int ks = 0; ks < 4; ks++) {
        const int kb = ks * 32 + (lane >> 4) * 16;
        uint32_t af[2][4], al[2][4];
#pragma unroll
        for (int mt = 0; mt < 2; mt++) {
            int row = wm + mt * 16 + (lane & 15);
            ldm_x4(aHiB + SWZ(row * 128 + kb), af[mt][0], af[mt][1], af[mt][2], af[mt][3]);
            ldm_x4(aLoB + SWZ(row * 128 + kb), al[mt][0], al[mt][1], al[mt][2], al[mt][3]);
        }
        uint32_t bf[4][2];
#pragma unroll
        for (int ng = 0; ng < 2; ng++) {
            int row = wn + ng * 16 + (lane & 15);
            uint32_t r0, r1, r2, r3;
            ldm_x4(bB + SWZ(row * 128 + kb), r0, r1, r2, r3);
            bf[ng * 2][0] = r0; bf[ng * 2 + 1][0] = r1;
            bf[ng * 2][1] = r2; bf[ng * 2 + 1][1] = r3;
        }
#pragma unroll
        for (int mt = 0; mt < 2; mt++)
#pragma unroll
            for (int nt = 0; nt < 4; nt++) {
                mma16816h(acc[mt][nt], af[mt], bf[nt][0], bf[nt][1]);
                mma16816h(acc[mt][nt], al[mt], bf[nt][0], bf[nt][1]);
            }
    }
}

// ---------------- per-step kernel: work queue over comm + cell items ----------------
// reads h from g_hA[t&1], writes h to g_hA[(t&1)^1]  (no intra-step h hazard)
// comm item (256, t>=1): ks=item&1, tile=item>>1 -> (a, m, n); 12 dc; partial -> g_connP[ks]; flag++
// cell item (128): (a, m, n); 10 dc; wait 2 flags; epilogue: P0+P1 -> connOut, tanh -> hist + hA-write
__global__ __launch_bounds__(256, 2) void step_kernel(int t, float* __restrict__ connOut,
                                                      int hasComm) {
    extern __shared__ char dsm[];
    __shared__ int s_item;
    uint32_t tiles = (smem_u32(dsm) + 1023) & ~1023u;
    const int tid = threadIdx.x, wid = tid >> 5, lane = tid & 31;
    const int wm = (wid & 1) * 32, wn = (wid >> 1) * 32;
    const int nItems = hasComm ? 384 : 128;
    const __half* xsT = g_xs + (size_t)t * B_ * 256;
    const __half* hRd = g_hA[t & 1];
    __half* hWr = g_hA[(t & 1) ^ 1];

    for (;;) {
        __syncthreads();
        if (tid == 0) s_item = atomicAdd(&g_qhead[t], 1);
        __syncthreads();
        const int item = s_item;
        if (item >= nItems) break;

        float acc[2][4][4];
#pragma unroll
        for (int i = 0; i < 2; i++)
#pragma unroll
            for (int j = 0; j < 4; j++)
#pragma unroll
                for (int q = 0; q < 4; q++) acc[i][j][q] = 0.0f;

        if (hasComm && item < 256) {
            // ---------------- comm item ----------------
            const int ks = item & 1, tile = item >> 1;
            const int a = tile >> 5, m = (tile >> 2) & 7, n = tile & 3;
            const int mBase = m * 64, nBase = n * 128;
            const __half* Brow = g_CWc + (size_t)a * NH * KCW;

            auto srcs = [&](int c, const __half*& hi, const __half*& lo, int& k0b) {
                int cc = ks * 12 + c;                 // 0..23
                int jj = cc >> 3, r8 = cc & 7;
                int j = jj + (jj >= a);
                int col = j * 512 + r8 * 64;
                hi = hRd + col; lo = hRd + 2048 + col;
                k0b = cc * 64;
            };

            const int C = 12;
            {
                const __half *h0, *l0; int kb0; srcs(0, h0, l0, kb0);
                load_dc(tiles, 0, tid, h0, KHA, l0, KHA, Brow, KCW, mBase, nBase, kb0);
                const __half *h1, *l1; int kb1; srcs(1, h1, l1, kb1);
                load_dc(tiles, 1, tid, h1, KHA, l1, KHA, Brow, KCW, mBase, nBase, kb1);
            }
            for (int c = 0; c < C; c++) {
                if (c < C - 1) CP_WAIT1(); else CP_WAIT0();
                __syncthreads();
                compute_dc(tiles + (c % 3) * STAGE, wm, wn, lane, acc);
                if (c + 2 < C) {
                    const __half *hs, *ls; int kb; srcs(c + 2, hs, ls, kb);
                    load_dc(tiles, (c + 2) % 3, tid, hs, KHA, ls, KHA, Brow, KCW, mBase, nBase, kb);
                }
            }
            float* P = g_connP[ks];
#pragma unroll
            for (int mt = 0; mt < 2; mt++)
#pragma unroll
                for (int nt = 0; nt < 4; nt++) {
                    const int r = mBase + wm + mt * 16 + (lane >> 2);
                    const int col = nBase + wn + nt * 8 + (lane & 3) * 2;
                    *(float2*)(P + ((size_t)a * B_ + r) * NH + col) =
                        make_float2(acc[mt][nt][0], acc[mt][nt][1]);
                    *(float2*)(P + ((size_t)a * B_ + r + 8) * NH + col) =
                        make_float2(acc[mt][nt][2], acc[mt][nt][3]);
                }
            __syncthreads();
            __threadfence();
            if (tid == 0) atomicAdd(&g_cflag[t][tile], 1);
        } else {
            // ---------------- cell item ----------------
            const int cidx = hasComm ? item - 256 : item;
            const int a = cidx >> 5, m = (cidx >> 2) & 7, n = cidx & 3;
            const int mBase = m * 64, nBase = n * 128;
            const __half* Brow = g_CWl + (size_t)a * NH * KLW;

            auto srcs = [&](int c, const __half*& hi, const __half*& lo, int& hs, int& k0b) {
                if (c < 8) { hi = hRd + a * 512 + c * 64; lo = hi + 2048; hs = KHA; }
                else       { hi = xsT + (c - 8) * 64;     lo = hi + 128;  hs = 256; }
                k0b = c * 64;
            };

            const int C = 10;
            {
                const __half *h0, *l0; int s0, kb0; srcs(0, h0, l0, s0, kb0);
                load_dc(tiles, 0, tid, h0, s0, l0, s0, Brow, KLW, mBase, nBase, kb0);
                const __half *h1, *l1; int s1, kb1; srcs(1, h1, l1, s1, kb1);
                load_dc(tiles, 1, tid, h1, s1, l1, s1, Brow, KLW, mBase, nBase, kb1);
            }
            for (int c = 0; c < C; c++) {
                if (c < C - 1) CP_WAIT1(); else CP_WAIT0();
                __syncthreads();
                compute_dc(tiles + (c % 3) * STAGE, wm, wn, lane, acc);
                if (c + 2 < C) {
                    const __half *hs, *ls; int ss, kb; srcs(c + 2, hs, ls, ss, kb);
                    load_dc(tiles, (c + 2) % 3, tid, hs, ss, ls, ss, Brow, KLW, mBase, nBase, kb);
                }
            }
            if (hasComm) {
                if (tid == 0)
                    while (atomicAdd(&g_cflag[t][cidx], 0) < 2) __nanosleep(32);
                __syncthreads();
                __threadfence();
            }
            // epilogue (writes hWr — never read within this step)
            float* hist = g_hist + (size_t)t * B_ * AH;
            const float* P0 = g_connP[0];
            const float* P1 = g_connP[1];
#pragma unroll
            for (int mt = 0; mt < 2; mt++)
#pragma unroll
                for (int nt = 0; nt < 4; nt++) {
                    const int r0 = mBase + wm + mt * 16 + (lane >> 2);
                    const int o = nBase + wn + nt * 8 + (lane & 3) * 2;
                    const float2 bias2 = *(const float2*)(g_bias + a * NH + o);
#pragma unroll
                    for (int h2 = 0; h2 < 2; h2++) {
                        const int b = r0 + h2 * 8;
                        float v0 = acc[mt][nt][h2 * 2 + 0] + bias2.x;
                        float v1 = acc[mt][nt][h2 * 2 + 1] + bias2.y;
                        if (hasComm) {
                            const size_t pidx = ((size_t)a * B_ + b) * NH + o;
                            const float2 c0 = *(const float2*)(P0 + pidx);
                            const float2 c1 = *(const float2*)(P1 + pidx);
                            const float cm0 = c0.x + c1.x, cm1 = c0.y + c1.y;
                            *(float2*)(connOut + pidx) = make_float2(cm0, cm1);
                            v0 += cm0; v1 += cm1;
                        }
                        v0 = tanhf(v0); v1 = tanhf(v1);
                        *(float2*)(hist + (size_t)b * AH + a * NH + o) = make_float2(v0, v1);
                        __half hh0 = __float2half(v0), hh1 = __float2half(v1);
                        __half ll0 = __float2half(v0 - __half2float(hh0));
                        __half ll1 = __float2half(v1 - __half2float(hh1));
                        __half* hp = hWr + (size_t)b * KHA + a * NH + o;
                        hp[0] = hh0; hp[1] = hh1;
                        hp[2048] = ll0; hp[2049] = ll1;
                    }
                }
        }
    }
}

// ---------------- readout over all timesteps ----------------
__global__ __launch_bounds__(256) void readout_all(const float* __restrict__ Wro,
                                                   const float* __restrict__ bro,
                                                   float* __restrict__ out_y) {
    __shared__ float sred[8][NOUT];
    const int b = blockIdx.x, t = blockIdx.y;
    const int tid = threadIdx.x;
    const float* hrow = g_hist + ((size_t)t * B_ + b) * AH;
    float acc[NOUT];
#pragma unroll
    for (int n = 0; n < NOUT; n++) acc[n] = 0.0f;
#pragma unroll
    for (int q = 0; q < 2; q++) {
        const int k = (q * 256 + tid) * 4;
        const float4 h4 = *(const float4*)(hrow + k);
#pragma unroll
        for (int n = 0; n < NOUT; n++) {
            const float4 w4 = __ldg((const float4*)(Wro + (size_t)n * AH + k));
            acc[n] += h4.x * w4.x + h4.y * w4.y + h4.z * w4.z + h4.w * w4.w;
        }
    }
    const int warp = tid >> 5, lane = tid & 31;
#pragma unroll
    for (int n = 0; n < NOUT; n++) {
#pragma unroll
        for (int off = 16; off > 0; off >>= 1)
            acc[n] += __shfl_xor_sync(0xFFFFFFFFu, acc[n], off);
        if (lane == 0) sred[warp][n] = acc[n];
    }
    __syncthreads();
    if (tid < NOUT) {
        float s = 0.0f;
#pragma unroll
        for (int w = 0; w < 8; w++) s += sred[w][tid];
        out_y[((size_t)t * B_ + b) * NOUT + tid] = s + bro[tid];
    }
}

// ---------------- h_final ----------------
__global__ void final_copy_kernel(float* __restrict__ hf) {
    const float* hlast = g_hist + (size_t)(TSTEPS - 1) * B_ * AH;
    const size_t stride = (size_t)blockDim.x * gridDim.x;
    for (size_t idx = (size_t)blockIdx.x * blockDim.x + threadIdx.x;
         idx < (size_t)NA * B_ * NH; idx += stride) {
        int o = (int)(idx & (NH - 1));
        int b = (int)((idx >> 9) & (B_ - 1));
        int a = (int)(idx >> 18);
        hf[idx] = hlast[(size_t)b * AH + a * NH + o];
    }
}

// ---------------- launch ----------------
extern "C" void kernel_launch(void* const* d_in, const int* in_sizes, int n_in,
                              void* d_out, int out_size) {
    const float* x   = (const float*)d_in[0];
    const float* Win = (const float*)d_in[1];
    const float* bin = (const float*)d_in[2];
    const float* Whh = (const float*)d_in[3];
    const float* bhh = (const float*)d_in[4];
    const float* Wc  = (const float*)d_in[5];
    const float* Wro = (const float*)d_in[6];
    const float* bro = (const float*)d_in[7];
    const void*  msk = d_in[8];

    float* out       = (float*)d_out;
    float* out_y     = out;
    float* out_hf    = out + (size_t)TSTEPS * B_ * NOUT;
    float* out_conn  = out_hf + (size_t)NA * B_ * NH;

    cudaFuncSetAttribute(step_kernel, cudaFuncAttributeMaxDynamicSharedMemorySize, SMEM_DYN);

    detect_mask_kernel<<<1, 256>>>((const unsigned char*)msk);
    prep_kernel<<<2048, 256>>>(x, Wc, msk, Whh, Win, bin, bhh);

    for (int t = 0; t < TSTEPS; t++) {
        float* connT = out_conn + (size_t)(t - 1) * NA * B_ * NH;
        step_kernel<<<296, 256, SMEM_DYN>>>(t, (t >= 1) ? connT : nullptr, (t >= 1) ? 1 : 0);
    }
    readout_all<<<dim3(B_, TSTEPS), 256>>>(Wro, bro, out_y);
    final_copy_kernel<<<512, 256>>>(out_hf);
}

// round 11
// speedup vs baseline: 4.5248x; 1.0366x over previous
// R11: persistent mega-kernel — all 64 timesteps in ONE launch, global work queue,
// cross-step software pipelining via celldone[t][m] counters. GEMM inner machinery
// (double-chunk shared-B HMMA), numerics (fp16 split-2), and epilogue identical to R10.
#include <cuda_runtime.h>
#include <cuda_fp16.h>
#include <cstdint>
#include <cstddef>

#define TSTEPS 64
#define B_     512
#define NA     4
#define NIN    128
#define NH     512
#define NOUT   10
#define AH     2048      // NA * NH
#define KHA    4096      // h split-2 width: [hi(2048)|lo(2048)]
#define KCW    1536      // comm weight width per agent (j != i)
#define KLW    640       // cell weight width: [Whh 512 | Win 128]
#define NITEMS (128 + (TSTEPS - 1) * 384)   // 24320

// ---------------- device scratch ----------------
__device__ __align__(1024) __half g_CWc[(size_t)NA * NH * KCW];    // comm W per target agent
__device__ __align__(1024) __half g_CWl[(size_t)NA * NH * KLW];    // cell W per agent
__device__ __align__(1024) __half g_xs[(size_t)TSTEPS * B_ * 256]; // x split: [t][b][hi128|lo128]
__device__ __align__(1024) __half g_hA[2][(size_t)B_ * KHA];       // h split, double-buffered
__device__ __align__(1024) float g_hist[(size_t)TSTEPS * B_ * AH]; // h history (f32)
__device__ __align__(1024) float g_connP[2][(size_t)NA * B_ * NH]; // comm split-K partials
__device__ __align__(1024) float g_bias[AH];
__device__ int g_qhead0;
__device__ int g_cflag[TSTEPS][128];     // per-step per-tile comm partial count (->2)
__device__ int g_celldone[TSTEPS][8];    // per-step per-row-block cell tile count (->16)
__device__ int g_mask_mode;

// ---------------- helpers ----------------
__device__ __forceinline__ uint32_t smem_u32(const void* p) {
    uint32_t a;
    asm("{ .reg .u64 t; cvta.to.shared.u64 t, %1; cvt.u32.u64 %0, t; }" : "=r"(a) : "l"(p));
    return a;
}
#define SWZ(x) ((x) ^ (((x) >> 3) & 0x70))

__device__ __forceinline__ void cp16(uint32_t dst, const void* src) {
    asm volatile("cp.async.cg.shared.global [%0], [%1], 16;" :: "r"(dst), "l"(src));
}
#define CP_COMMIT() asm volatile("cp.async.commit_group;" ::: "memory")
#define CP_WAIT1()  asm volatile("cp.async.wait_group 1;" ::: "memory")
#define CP_WAIT0()  asm volatile("cp.async.wait_group 0;" ::: "memory")

__device__ __forceinline__ void ldm_x4(uint32_t addr, uint32_t& r0, uint32_t& r1,
                                       uint32_t& r2, uint32_t& r3) {
    asm volatile("ldmatrix.sync.aligned.m8n8.x4.shared.b16 {%0,%1,%2,%3}, [%4];"
                 : "=r"(r0), "=r"(r1), "=r"(r2), "=r"(r3) : "r"(addr));
}
__device__ __forceinline__ void mma16816h(float* c, const uint32_t* a, uint32_t b0, uint32_t b1) {
    asm volatile("mma.sync.aligned.m16n8k16.row.col.f32.f16.f16.f32 "
                 "{%0,%1,%2,%3}, {%4,%5,%6,%7}, {%8,%9}, {%0,%1,%2,%3};"
                 : "+f"(c[0]), "+f"(c[1]), "+f"(c[2]), "+f"(c[3])
                 : "r"(a[0]), "r"(a[1]), "r"(a[2]), "r"(a[3]), "r"(b0), "r"(b1));
}
__device__ __forceinline__ void spin_until(int* p, int target) {
    while (atomicAdd(p, 0) < target) __nanosleep(32);
}

// ---------------- mask dtype detection ----------------
__global__ void detect_mask_kernel(const unsigned char* __restrict__ m) {
    __shared__ int c1, c2;
    if (threadIdx.x == 0) { c1 = 0; c2 = 0; }
    __syncthreads();
    int l1 = 0, l2 = 0;
    for (int i = threadIdx.x; i < 16384; i += blockDim.x) {
        if (m[4 * i + 1]) l1++;
        if (m[4 * i + 2] | m[4 * i + 3]) l2++;
    }
    atomicAdd(&c1, l1);
    atomicAdd(&c2, l2);
    __syncthreads();
    if (threadIdx.x == 0) g_mask_mode = (c1 > 0) ? 0 : ((c2 > 0) ? 1 : 2);
}

// ---------------- prep ----------------
__global__ void prep_kernel(const float* __restrict__ x,
                            const float* __restrict__ Wc, const void* __restrict__ maskv,
                            const float* __restrict__ Whh, const float* __restrict__ Win,
                            const float* __restrict__ bin, const float* __restrict__ bhh) {
    const int mode = g_mask_mode;
    const unsigned char* m8 = (const unsigned char*)maskv;
    const float*         mf = (const float*)maskv;
    const int*           mi = (const int*)maskv;
    const size_t stride = (size_t)blockDim.x * gridDim.x;
    const size_t t0 = (size_t)blockIdx.x * blockDim.x + threadIdx.x;

    // comm weights: g_CWc[i][o][k], k = jj*512 + h, j = jj + (jj>=i); fp16(w*0.1)
    for (size_t idx = t0; idx < (size_t)NA * NH * KCW; idx += stride) {
        int k = (int)(idx % KCW);
        int r = (int)(idx / KCW);
        int o = r & (NH - 1);
        int i = r >> 9;
        int jj = k >> 9, h = k & (NH - 1);
        int j = jj + (jj >= i);
        size_t widx = (((size_t)j * NA + i) * NH + h) * NH + o;
        bool msk = (mode == 0) ? (m8[widx] != 0)
                 : (mode == 1) ? (mf[widx] != 0.0f)
                               : (mi[widx] != 0);
        g_CWc[idx] = __float2half(msk ? Wc[widx] * 0.1f : 0.0f);
    }
    // cell weights: g_CWl[a][o][k]: k<512 -> Whh[a][o][k]; else Win[a][o][k-512]
    for (size_t idx = t0; idx < (size_t)NA * NH * KLW; idx += stride) {
        int k = (int)(idx % KLW);
        int r = (int)(idx / KLW);
        int o = r & (NH - 1);
        int a = r >> 9;
        float w = (k < NH) ? Whh[((size_t)a * NH + o) * NH + k]
                           : Win[((size_t)a * NH + o) * NIN + (k - NH)];
        g_CWl[idx] = __float2half(w);
    }
    // x split-2 fp16
    for (size_t idx = t0; idx < (size_t)TSTEPS * B_ * NIN; idx += stride) {
        int k = (int)(idx & (NIN - 1));
        size_t tb = idx >> 7;
        float v = x[idx];
        __half hi = __float2half(v);
        __half lo = __float2half(v - __half2float(hi));
        __half* row = g_xs + tb * 256;
        row[k] = hi; row[128 + k] = lo;
    }
    for (size_t idx = t0; idx < (size_t)AH; idx += stride)
        g_bias[idx] = bin[idx] + bhh[idx];
    // zero h buffer 0 (read at t=0); buffer 1 fully rewritten by cell(0) before any t=1 reader
    uint32_t* hA32 = (uint32_t*)g_hA[0];
    for (size_t idx = t0; idx < (size_t)B_ * KHA / 2; idx += stride)
        hA32[idx] = 0u;
    if (t0 == 0) g_qhead0 = 0;
    for (size_t idx = t0; idx < (size_t)TSTEPS * 128; idx += stride)
        ((int*)g_cflag)[idx] = 0;
    for (size_t idx = t0; idx < (size_t)TSTEPS * 8; idx += stride)
        ((int*)g_celldone)[idx] = 0;
}

// ---------------- double-chunk HMMA machinery ----------------
// stage: A_hi 64x64 (8KB) @0, A_lo 64x64 @8192, B 128x64 (16KB) @16384
#define STAGE 32768
#define SMEM_DYN (3 * STAGE + 1024)

__device__ __forceinline__ void load_dc(uint32_t tiles, int s, int tid,
                                        const __half* aHi, int aHiStride,
                                        const __half* aLo, int aLoStride,
                                        const __half* bRow, int bStride,
                                        int mBase, int nBase, int k0b) {
    uint32_t base = tiles + s * STAGE;
#pragma unroll
    for (int u = 0; u < 2; u++) {
        int i = tid * 2 + u;              // 0..511
        int r = i >> 3, g = i & 7;
        cp16(base + SWZ(r * 128 + g * 16), aHi + (size_t)(mBase + r) * aHiStride + g * 8);
    }
#pragma unroll
    for (int u = 0; u < 2; u++) {
        int i = tid * 2 + u;
        int r = i >> 3, g = i & 7;
        cp16(base + 8192 + SWZ(r * 128 + g * 16), aLo + (size_t)(mBase + r) * aLoStride + g * 8);
    }
#pragma unroll
    for (int u = 0; u < 4; u++) {
        int i = tid * 4 + u;              // 0..1023
        int r = i >> 3, g = i & 7;
        cp16(base + 16384 + SWZ(r * 128 + g * 16), bRow + (size_t)(nBase + r) * bStride + k0b + g * 8);
    }
    CP_COMMIT();
}

__device__ __forceinline__ void compute_dc(uint32_t st, int wm, int wn, int lane,
                                           float acc[2][4][4]) {
    const uint32_t aHiB = st, aLoB = st + 8192, bB = st + 16384;
#pragma unroll
    for (int ks = 0; ks < 4; ks++) {
        const int kb = ks * 32 + (lane >> 4) * 16;
        uint32_t af[2][4], al[2][4];
#pragma unroll
        for (int mt = 0; mt < 2; mt++) {
            int row = wm + mt * 16 + (lane & 15);
            ldm_x4(aHiB + SWZ(row * 128 + kb), af[mt][0], af[mt][1], af[mt][2], af[mt][3]);
            ldm_x4(aLoB + SWZ(row * 128 + kb), al[mt][0], al[mt][1], al[mt][2], al[mt][3]);
        }
        uint32_t bf[4][2];
#pragma unroll
        for (int ng = 0; ng < 2; ng++) {
            int row = wn + ng * 16 + (lane & 15);
            uint32_t r0, r1, r2, r3;
            ldm_x4(bB + SWZ(row * 128 + kb), r0, r1, r2, r3);
            bf[ng * 2][0] = r0; bf[ng * 2 + 1][0] = r1;
            bf[ng * 2][1] = r2; bf[ng * 2 + 1][1] = r3;
        }
#pragma unroll
        for (int mt = 0; mt < 2; mt++)
#pragma unroll
            for (int nt = 0; nt < 4; nt++) {
                mma16816h(acc[mt][nt], af[mt], bf[nt][0], bf[nt][1]);
                mma16816h(acc[mt][nt], al[mt], bf[nt][0], bf[nt][1]);
            }
    }
}

// ---------------- persistent mega-kernel: global queue over all steps ----------------
// item idx < 128                  -> t=0 cell tile idx
// else r=idx-128, t=1+r/384, q=r%384: q<256 -> comm (ks=q&1, tile=q>>1); else cell tile q-256
// comm(t):  wait celldone[t-1][m]==16; K=1536 split-K half; partial -> g_connP[ks]; cflag++
// cell(t):  wait celldone[t-1][m]==16 (t>0); GEMM K=1280; wait cflag==2 (t>0);
//           epilogue -> connOut + hist + hA[(t&1)^1]; then celldone[t][m]++
__global__ __launch_bounds__(256, 2) void mega_kernel(float* __restrict__ connBase) {
    extern __shared__ char dsm[];
    __shared__ int s_item;
    uint32_t tiles = (smem_u32(dsm) + 1023) & ~1023u;
    const int tid = threadIdx.x, wid = tid >> 5, lane = tid & 31;
    const int wm = (wid & 1) * 32, wn = (wid >> 1) * 32;

    for (;;) {
        __syncthreads();
        if (tid == 0) s_item = atomicAdd(&g_qhead0, 1);
        __syncthreads();
        const int idx = s_item;
        if (idx >= NITEMS) break;

        int t, q;
        if (idx < 128) { t = 0; q = 256 + idx; }
        else { int r = idx - 128; t = 1 + r / 384; q = r % 384; }

        const __half* hRd = g_hA[t & 1];
        __half* hWr = g_hA[(t & 1) ^ 1];
        const __half* xsT = g_xs + (size_t)t * B_ * 256;

        float acc[2][4][4];
#pragma unroll
        for (int i = 0; i < 2; i++)
#pragma unroll
            for (int j = 0; j < 4; j++)
#pragma unroll
                for (int qq = 0; qq < 4; qq++) acc[i][j][qq] = 0.0f;

        if (q < 256) {
            // ---------------- comm item (t >= 1) ----------------
            const int ks = q & 1, tile = q >> 1;
            const int a = tile >> 5, m = (tile >> 2) & 7, n = tile & 3;
            const int mBase = m * 64, nBase = n * 128;
            const __half* Brow = g_CWc + (size_t)a * NH * KCW;

            // h(t-1) rows of this block must be fully written
            if (tid == 0) spin_until(&g_celldone[t - 1][m], 16);
            __syncthreads();
            __threadfence();

            auto srcs = [&](int c, const __half*& hi, const __half*& lo, int& k0b) {
                int cc = ks * 12 + c;                 // 0..23
                int jj = cc >> 3, r8 = cc & 7;
                int j = jj + (jj >= a);
                int col = j * 512 + r8 * 64;
                hi = hRd + col; lo = hRd + 2048 + col;
                k0b = cc * 64;
            };

            const int C = 12;
            {
                const __half *h0, *l0; int kb0; srcs(0, h0, l0, kb0);
                load_dc(tiles, 0, tid, h0, KHA, l0, KHA, Brow, KCW, mBase, nBase, kb0);
                const __half *h1, *l1; int kb1; srcs(1, h1, l1, kb1);
                load_dc(tiles, 1, tid, h1, KHA, l1, KHA, Brow, KCW, mBase, nBase, kb1);
            }
            for (int c = 0; c < C; c++) {
                if (c < C - 1) CP_WAIT1(); else CP_WAIT0();
                __syncthreads();
                compute_dc(tiles + (c % 3) * STAGE, wm, wn, lane, acc);
                if (c + 2 < C) {
                    const __half *hs, *ls; int kb; srcs(c + 2, hs, ls, kb);
                    load_dc(tiles, (c + 2) % 3, tid, hs, KHA, ls, KHA, Brow, KCW, mBase, nBase, kb);
                }
            }
            float* P = g_connP[ks];
#pragma unroll
            for (int mt = 0; mt < 2; mt++)
#pragma unroll
                for (int nt = 0; nt < 4; nt++) {
                    const int r = mBase + wm + mt * 16 + (lane >> 2);
                    const int col = nBase + wn + nt * 8 + (lane & 3) * 2;
                    *(float2*)(P + ((size_t)a * B_ + r) * NH + col) =
                        make_float2(acc[mt][nt][0], acc[mt][nt][1]);
                    *(float2*)(P + ((size_t)a * B_ + r + 8) * NH + col) =
                        make_float2(acc[mt][nt][2], acc[mt][nt][3]);
                }
            __syncthreads();
            __threadfence();
            if (tid == 0) atomicAdd(&g_cflag[t][tile], 1);
        } else {
            // ---------------- cell item ----------------
            const int cidx = q - 256;
            const int a = cidx >> 5, m = (cidx >> 2) & 7, n = cidx & 3;
            const int mBase = m * 64, nBase = n * 128;
            const __half* Brow = g_CWl + (size_t)a * NH * KLW;

            if (t > 0) {
                if (tid == 0) spin_until(&g_celldone[t - 1][m], 16);
                __syncthreads();
                __threadfence();
            }

            auto srcs = [&](int c, const __half*& hi, const __half*& lo, int& hs, int& k0b) {
                if (c < 8) { hi = hRd + a * 512 + c * 64; lo = hi + 2048; hs = KHA; }
                else       { hi = xsT + (c - 8) * 64;     lo = hi + 128;  hs = 256; }
                k0b = c * 64;
            };

            const int C = 10;
            {
                const __half *h0, *l0; int s0, kb0; srcs(0, h0, l0, s0, kb0);
                load_dc(tiles, 0, tid, h0, s0, l0, s0, Brow, KLW, mBase, nBase, kb0);
                const __half *h1, *l1; int s1, kb1; srcs(1, h1, l1, s1, kb1);
                load_dc(tiles, 1, tid, h1, s1, l1, s1, Brow, KLW, mBase, nBase, kb1);
            }
            for (int c = 0; c < C; c++) {
                if (c < C - 1) CP_WAIT1(); else CP_WAIT0();
                __syncthreads();
                compute_dc(tiles + (c % 3) * STAGE, wm, wn, lane, acc);
                if (c + 2 < C) {
                    const __half *hs, *ls; int ss, kb; srcs(c + 2, hs, ls, ss, kb);
                    load_dc(tiles, (c + 2) % 3, tid, hs, ss, ls, ss, Brow, KLW, mBase, nBase, kb);
                }
            }
            if (t > 0) {
                if (tid == 0) spin_until(&g_cflag[t][cidx], 2);
                __syncthreads();
                __threadfence();
            }
            // epilogue (writes hWr — never read within this step)
            float* hist = g_hist + (size_t)t * B_ * AH;
            float* connT = connBase + (size_t)(t - 1) * NA * B_ * NH;   // valid for t>=1
            const float* P0 = g_connP[0];
            const float* P1 = g_connP[1];
#pragma unroll
            for (int mt = 0; mt < 2; mt++)
#pragma unroll
                for (int nt = 0; nt < 4; nt++) {
                    const int r0 = mBase + wm + mt * 16 + (lane >> 2);
                    const int o = nBase + wn + nt * 8 + (lane & 3) * 2;
                    const float2 bias2 = *(const float2*)(g_bias + a * NH + o);
#pragma unroll
                    for (int h2 = 0; h2 < 2; h2++) {
                        const int b = r0 + h2 * 8;
                        float v0 = acc[mt][nt][h2 * 2 + 0] + bias2.x;
                        float v1 = acc[mt][nt][h2 * 2 + 1] + bias2.y;
                        if (t > 0) {
                            const size_t pidx = ((size_t)a * B_ + b) * NH + o;
                            const float2 c0 = *(const float2*)(P0 + pidx);
                            const float2 c1 = *(const float2*)(P1 + pidx);
                            const float cm0 = c0.x + c1.x, cm1 = c0.y + c1.y;
                            *(float2*)(connT + pidx) = make_float2(cm0, cm1);
                            v0 += cm0; v1 += cm1;
                        }
                        v0 = tanhf(v0); v1 = tanhf(v1);
                        *(float2*)(hist + (size_t)b * AH + a * NH + o) = make_float2(v0, v1);
                        __half hh0 = __float2half(v0), hh1 = __float2half(v1);
                        __half ll0 = __float2half(v0 - __half2float(hh0));
                        __half ll1 = __float2half(v1 - __half2float(hh1));
                        __half* hp = hWr + (size_t)b * KHA + a * NH + o;
                        hp[0] = hh0; hp[1] = hh1;
                        hp[2048] = ll0; hp[2049] = ll1;
                    }
                }
            __syncthreads();
            __threadfence();
            if (tid == 0) atomicAdd(&g_celldone[t][m], 1);
        }
    }
}

// ---------------- readout over all timesteps ----------------
__global__ __launch_bounds__(256) void readout_all(const float* __restrict__ Wro,
                                                   const float* __restrict__ bro,
                                                   float* __restrict__ out_y) {
    __shared__ float sred[8][NOUT];
    const int b = blockIdx.x, t = blockIdx.y;
    const int tid = threadIdx.x;
    const float* hrow = g_hist + ((size_t)t * B_ + b) * AH;
    float acc[NOUT];
#pragma unroll
    for (int n = 0; n < NOUT; n++) acc[n] = 0.0f;
#pragma unroll
    for (int q = 0; q < 2; q++) {
        const int k = (q * 256 + tid) * 4;
        const float4 h4 = *(const float4*)(hrow + k);
#pragma unroll
        for (int n = 0; n < NOUT; n++) {
            const float4 w4 = __ldg((const float4*)(Wro + (size_t)n * AH + k));
            acc[n] += h4.x * w4.x + h4.y * w4.y + h4.z * w4.z + h4.w * w4.w;
        }
    }
    const int warp = tid >> 5, lane = tid & 31;
#pragma unroll
    for (int n = 0; n < NOUT; n++) {
#pragma unroll
        for (int off = 16; off > 0; off >>= 1)
            acc[n] += __shfl_xor_sync(0xFFFFFFFFu, acc[n], off);
        if (lane == 0) sred[warp][n] = acc[n];
    }
    __syncthreads();
    if (tid < NOUT) {
        float s = 0.0f;
#pragma unroll
        for (int w = 0; w < 8; w++) s += sred[w][tid];
        out_y[((size_t)t * B_ + b) * NOUT + tid] = s + bro[tid];
    }
}

// ---------------- h_final ----------------
__global__ void final_copy_kernel(float* __restrict__ hf) {
    const float* hlast = g_hist + (size_t)(TSTEPS - 1) * B_ * AH;
    const size_t stride = (size_t)blockDim.x * gridDim.x;
    for (size_t idx = (size_t)blockIdx.x * blockDim.x + threadIdx.x;
         idx < (size_t)NA * B_ * NH; idx += stride) {
        int o = (int)(idx & (NH - 1));
        int b = (int)((idx >> 9) & (B_ - 1));
        int a = (int)(idx >> 18);
        hf[idx] = hlast[(size_t)b * AH + a * NH + o];
    }
}

// ---------------- launch ----------------
extern "C" void kernel_launch(void* const* d_in, const int* in_sizes, int n_in,
                              void* d_out, int out_size) {
    const float* x   = (const float*)d_in[0];
    const float* Win = (const float*)d_in[1];
    const float* bin = (const float*)d_in[2];
    const float* Whh = (const float*)d_in[3];
    const float* bhh = (const float*)d_in[4];
    const float* Wc  = (const float*)d_in[5];
    const float* Wro = (const float*)d_in[6];
    const float* bro = (const float*)d_in[7];
    const void*  msk = d_in[8];

    float* out       = (float*)d_out;
    float* out_y     = out;
    float* out_hf    = out + (size_t)TSTEPS * B_ * NOUT;
    float* out_conn  = out_hf + (size_t)NA * B_ * NH;

    cudaFuncSetAttribute(mega_kernel, cudaFuncAttributeMaxDynamicSharedMemorySize, SMEM_DYN);

    detect_mask_kernel<<<1, 256>>>((const unsigned char*)msk);
    prep_kernel<<<2048, 256>>>(x, Wc, msk, Whh, Win, bin, bhh);
    mega_kernel<<<296, 256, SMEM_DYN>>>(out_conn);
    readout_all<<<dim3(B_, TSTEPS), 256>>>(Wro, bro, out_y);
    final_copy_kernel<<<512, 256>>>(out_hf);
}